// round 3
// baseline (speedup 1.0000x reference)
#include <cuda_runtime.h>
#include <cuda_bf16.h>

// ---------------- problem constants (fixed-shape problem) ----------------
#define MAXN 100000
#define MAXE 1600000
#define INF_DIM 128
#define OUTF 128          // H*D
#define NHEAD 4

// ---------------- device scratch (no allocations allowed) ----------------
__device__ __align__(16) float  g_h[(size_t)MAXN * OUTF];   // 51.2 MB
__device__ __align__(16) float  g_sl[(size_t)MAXN * NHEAD];
__device__ __align__(16) float  g_sr[(size_t)MAXN * NHEAD];
__device__ int    g_deg[MAXN];
__device__ int    g_rowptr[MAXN + 1];
__device__ int    g_cursor[MAXN];
__device__ int    g_bsum[256];
__device__ int    g_src[MAXE];                    // 6.4 MB
__device__ int    g_dst[MAXE];                    // 6.4 MB
__device__ int    g_csr_src[MAXE];                // 6.4 MB
__device__ __align__(16) float4 g_csr_ee[MAXE];   // 25.6 MB

// ---------------- K0: normalize edge_index (int32 vs int64, clamp) -------
// Reference requests int64 but JAX x64-off silently makes int32. Detect the
// layout device-side: for little-endian int64 values in [0, 2^31), the odd
// int32 words of the first 64 entries are all zero; for int32 data they are
// 64 random node ids (all-zero probability ~1e-320).
__global__ void normalize_kernel(const int* __restrict__ raw,
                                 int n_edges, int n_nodes)
{
    __shared__ int is64_sh;
    if (threadIdx.x == 0) {
        int acc = 0;
        for (int i = 0; i < 64; ++i) acc |= raw[2 * i + 1];
        is64_sh = (acc == 0) ? 1 : 0;
    }
    __syncthreads();
    int is64 = is64_sh;
    int e = blockIdx.x * blockDim.x + threadIdx.x;
    if (e >= n_edges) return;
    int s, d;
    if (is64) {
        s = raw[(size_t)e * 2];                    // low word of src[e]
        d = raw[((size_t)n_edges + e) * 2];        // low word of dst[e]
    } else {
        s = raw[e];
        d = raw[n_edges + e];
    }
    s = min(max(s, 0), n_nodes - 1);
    d = min(max(d, 0), n_nodes - 1);
    g_src[e] = s;
    g_dst[e] = d;
}

// ---------------- K1: h = x @ W^T  (fp32, 128x128 tile, 8x8 microtile) ----
__global__ __launch_bounds__(256, 2)
void gemm_kernel(const float* __restrict__ x, const float* __restrict__ W,
                 int n_nodes)
{
    // stride 128 floats: rows 512B-aligned -> LDS.128 legal; all inner-loop
    // shared reads are within one row k (conflict-free broadcast pattern).
    __shared__ float xs[32][128];
    __shared__ float ws[32][128];

    const int tid = threadIdx.x;
    const int tc  = tid & 15;
    const int tr  = tid >> 4;
    const int n0  = blockIdx.x * 128;

    float acc[8][8];
#pragma unroll
    for (int i = 0; i < 8; ++i)
#pragma unroll
        for (int j = 0; j < 8; ++j) acc[i][j] = 0.f;

    for (int kt = 0; kt < INF_DIM; kt += 32) {
#pragma unroll
        for (int i = 0; i < 4; ++i) {
            int flat = i * 256 + tid;        // float4 index 0..1023
            int n    = flat & 127;
            int kb   = (flat >> 7) * 4;
            float4 v = make_float4(0.f, 0.f, 0.f, 0.f);
            int gn = n0 + n;
            if (gn < n_nodes)
                v = *(const float4*)&x[(size_t)gn * INF_DIM + kt + kb];
            xs[kb + 0][n] = v.x; xs[kb + 1][n] = v.y;
            xs[kb + 2][n] = v.z; xs[kb + 3][n] = v.w;
            float4 wv = *(const float4*)&W[(size_t)n * INF_DIM + kt + kb];
            ws[kb + 0][n] = wv.x; ws[kb + 1][n] = wv.y;
            ws[kb + 2][n] = wv.z; ws[kb + 3][n] = wv.w;
        }
        __syncthreads();

#pragma unroll 4
        for (int k = 0; k < 32; ++k) {
            float4 a0 = *(const float4*)&xs[k][tr * 4];
            float4 a1 = *(const float4*)&xs[k][tr * 4 + 64];
            float4 b0 = *(const float4*)&ws[k][tc * 4];
            float4 b1 = *(const float4*)&ws[k][tc * 4 + 64];
            float a[8] = {a0.x, a0.y, a0.z, a0.w, a1.x, a1.y, a1.z, a1.w};
            float b[8] = {b0.x, b0.y, b0.z, b0.w, b1.x, b1.y, b1.z, b1.w};
#pragma unroll
            for (int i = 0; i < 8; ++i)
#pragma unroll
                for (int j = 0; j < 8; ++j)
                    acc[i][j] += a[i] * b[j];
        }
        __syncthreads();
    }

#pragma unroll
    for (int i = 0; i < 8; ++i) {
        int row = (i < 4) ? (tr * 4 + i) : (tr * 4 + 64 + (i - 4));
        int gn  = n0 + row;
        if (gn < n_nodes) {
            float4 o0 = make_float4(acc[i][0], acc[i][1], acc[i][2], acc[i][3]);
            float4 o1 = make_float4(acc[i][4], acc[i][5], acc[i][6], acc[i][7]);
            *(float4*)&g_h[(size_t)gn * OUTF + tc * 4]      = o0;
            *(float4*)&g_h[(size_t)gn * OUTF + tc * 4 + 64] = o1;
        }
    }
}

// ---------------- K2: per-node attention scalars + zero deg --------------
__global__ void scalars_kernel(const float* __restrict__ al,
                               const float* __restrict__ ar, int n_nodes)
{
    int warp = (blockIdx.x * blockDim.x + threadIdx.x) >> 5;
    int lane = threadIdx.x & 31;
    if (warp >= n_nodes) return;
    float4 hv  = *(const float4*)&g_h[(size_t)warp * OUTF + lane * 4];
    float4 alv = *(const float4*)&al[lane * 4];   // [H,D] flat == lane*4
    float4 arv = *(const float4*)&ar[lane * 4];
    float sl = hv.x * alv.x + hv.y * alv.y + hv.z * alv.z + hv.w * alv.w;
    float sr = hv.x * arv.x + hv.y * arv.y + hv.z * arv.z + hv.w * arv.w;
#pragma unroll
    for (int off = 4; off >= 1; off >>= 1) {
        sl += __shfl_xor_sync(0xffffffffu, sl, off);
        sr += __shfl_xor_sync(0xffffffffu, sr, off);
    }
    if ((lane & 7) == 0) {
        g_sl[warp * NHEAD + (lane >> 3)] = sl;
        g_sr[warp * NHEAD + (lane >> 3)] = sr;
    }
    if (lane == 0) g_deg[warp] = 0;
}

// ---------------- K3: in-degree histogram ---------------------------------
__global__ void hist_kernel(int n_edges)
{
    int e = blockIdx.x * blockDim.x + threadIdx.x;
    if (e < n_edges)
        atomicAdd(&g_deg[g_dst[e]], 1);
}

// ---------------- K4/K5/K6: exclusive scan (1024-chunk blocks) -----------
__global__ __launch_bounds__(1024)
void scan1_kernel(int n_nodes)
{
    __shared__ int sh[1024];
    int i = blockIdx.x * 1024 + threadIdx.x;
    int v = (i < n_nodes) ? g_deg[i] : 0;
    sh[threadIdx.x] = v;
    __syncthreads();
    int xval = v;
#pragma unroll
    for (int off = 1; off < 1024; off <<= 1) {
        int t = (threadIdx.x >= off) ? sh[threadIdx.x - off] : 0;
        __syncthreads();
        xval += t;
        sh[threadIdx.x] = xval;
        __syncthreads();
    }
    if (i < n_nodes) g_rowptr[i] = xval - v;   // local exclusive
    if (threadIdx.x == 1023) g_bsum[blockIdx.x] = xval;
}

__global__ void scan2_kernel(int nblocks)
{
    if (blockIdx.x == 0 && threadIdx.x == 0) {
        int run = 0;
        for (int b = 0; b < nblocks; ++b) {
            int t = g_bsum[b];
            g_bsum[b] = run;
            run += t;
        }
    }
}

__global__ void scan3_kernel(int n_nodes, int n_edges)
{
    int i = blockIdx.x * blockDim.x + threadIdx.x;
    if (i < n_nodes) {
        int r = g_rowptr[i] + g_bsum[i >> 10];
        g_rowptr[i] = r;
        g_cursor[i] = r;
    }
    if (i == 0) g_rowptr[n_nodes] = n_edges;
}

// ---------------- K7: edge scatter (compute e_exp, place into CSR) -------
__device__ __forceinline__ float lrelu_exp(float a)
{
    float t = (a > 0.f) ? a : 0.2f * a;
    return __expf(t);
}

__global__ void scatter_kernel(int n_edges)
{
    int e = blockIdx.x * blockDim.x + threadIdx.x;
    if (e >= n_edges) return;
    int s = g_src[e];
    int d = g_dst[e];
    float4 sl = *(const float4*)&g_sl[(size_t)s * NHEAD];
    float4 sr = *(const float4*)&g_sr[(size_t)d * NHEAD];
    float4 ee;
    ee.x = lrelu_exp(sl.x + sr.x);
    ee.y = lrelu_exp(sl.y + sr.y);
    ee.z = lrelu_exp(sl.z + sr.z);
    ee.w = lrelu_exp(sl.w + sr.w);
    int pos = atomicAdd(&g_cursor[d], 1);
    pos = min(max(pos, 0), MAXE - 1);   // defensive
    g_csr_src[pos] = s;
    g_csr_ee[pos]  = ee;
}

// ---------------- K8: warp-per-node aggregation (no float atomics) -------
__global__ __launch_bounds__(256)
void aggregate_kernel(float* __restrict__ out, int n_nodes, int n_edges)
{
    int warp = (blockIdx.x * blockDim.x + threadIdx.x) >> 5;
    int lane = threadIdx.x & 31;
    if (warp >= n_nodes) return;

    int beg = g_rowptr[warp];
    int end = g_rowptr[warp + 1];
    beg = min(max(beg, 0), n_edges);    // defensive
    end = min(max(end, beg), n_edges);
    int head = lane >> 3;

    const float4* __restrict__ h4 = (const float4*)g_h;
    const float*  __restrict__ eearr = (const float*)g_csr_ee;

    float4 acc = make_float4(0.f, 0.f, 0.f, 0.f);
    float den = 0.f;

    int j = beg;
    int s = 0; float ee = 0.f;
    if (j < end) {
        s  = g_csr_src[j];
        ee = eearr[(size_t)j * 4 + head];
    }
    while (j < end) {
        float4 v = h4[(size_t)s * 32 + lane];
        int jn = j + 1;
        int sn = 0; float een = 0.f;
        if (jn < end) {
            sn  = g_csr_src[jn];
            een = eearr[(size_t)jn * 4 + head];
        }
        acc.x += v.x * ee; acc.y += v.y * ee;
        acc.z += v.z * ee; acc.w += v.w * ee;
        den += ee;
        s = sn; ee = een; j = jn;
    }

    float inv = 1.f / (den + 1e-8f);
    float4 o = make_float4(acc.x * inv, acc.y * inv, acc.z * inv, acc.w * inv);
    *(float4*)&out[(size_t)warp * OUTF + lane * 4] = o;
}

// ---------------- launch ---------------------------------------------------
extern "C" void kernel_launch(void* const* d_in, const int* in_sizes, int n_in,
                              void* d_out, int out_size)
{
    const float* x   = (const float*)d_in[0];
    const int*   ei  = (const int*)d_in[1];     // int32 OR int64 (detected)
    const float* W   = (const float*)d_in[2];
    const float* al  = (const float*)d_in[3];
    const float* ar  = (const float*)d_in[4];
    float* out = (float*)d_out;

    int n_nodes = in_sizes[0] / INF_DIM;
    int n_edges = in_sizes[1] / 2;
    if (n_nodes > MAXN) n_nodes = MAXN;
    if (n_edges > MAXE) n_edges = MAXE;

    // K0: normalize edge indices (dtype-robust, clamped)
    normalize_kernel<<<(n_edges + 255) / 256, 256>>>(ei, n_edges, n_nodes);

    // K1: GEMM
    int gemm_blocks = (n_nodes + 127) / 128;
    gemm_kernel<<<gemm_blocks, 256>>>(x, W, n_nodes);

    // K2: node scalars + zero deg
    int warps_blocks = (n_nodes * 32 + 255) / 256;
    scalars_kernel<<<warps_blocks, 256>>>(al, ar, n_nodes);

    // K3: histogram
    hist_kernel<<<(n_edges + 255) / 256, 256>>>(n_edges);

    // K4-6: scan -> rowptr, cursor
    int scan_blocks = (n_nodes + 1023) / 1024;
    scan1_kernel<<<scan_blocks, 1024>>>(n_nodes);
    scan2_kernel<<<1, 32>>>(scan_blocks);
    scan3_kernel<<<(n_nodes + 255) / 256, 256>>>(n_nodes, n_edges);

    // K7: scatter edges into CSR with e_exp
    scatter_kernel<<<(n_edges + 255) / 256, 256>>>(n_edges);

    // K8: aggregate
    aggregate_kernel<<<warps_blocks, 256>>>(out, n_nodes, n_edges);
}

// round 4
// speedup vs baseline: 1.0857x; 1.0857x over previous
#include <cuda_runtime.h>
#include <cuda_bf16.h>

// ---------------- problem constants (fixed-shape problem) ----------------
#define MAXN 100000
#define MAXE 1600000
#define INF_DIM 128
#define OUTF 128          // H*D
#define NHEAD 4

typedef unsigned long long u64;

// ---------------- device scratch (no allocations allowed) ----------------
__device__ __align__(16) float  g_h[(size_t)MAXN * OUTF];   // 51.2 MB
__device__ __align__(16) float  g_sl[(size_t)MAXN * NHEAD];
__device__ __align__(16) float  g_sr[(size_t)MAXN * NHEAD];
__device__ int    g_deg[MAXN];
__device__ int    g_rowptr[MAXN + 1];
__device__ int    g_cursor[MAXN];
__device__ int    g_bsum[256];
__device__ int    g_src[MAXE];                    // 6.4 MB
__device__ int    g_dst[MAXE];                    // 6.4 MB
__device__ int    g_csr_src[MAXE];                // 6.4 MB

// ---------------- f32x2 helpers (sm_103a packed fp32 pipe) ----------------
__device__ __forceinline__ u64 pack2(float lo, float hi) {
    u64 r; asm("mov.b64 %0, {%1, %2};" : "=l"(r) : "f"(lo), "f"(hi)); return r;
}
__device__ __forceinline__ u64 fma2(u64 a, u64 b, u64 c) {
    u64 d; asm("fma.rn.f32x2 %0, %1, %2, %3;" : "=l"(d) : "l"(a), "l"(b), "l"(c));
    return d;
}
__device__ __forceinline__ float2 unpack2(u64 v) {
    float2 f; asm("mov.b64 {%0, %1}, %2;" : "=f"(f.x), "=f"(f.y) : "l"(v));
    return f;
}

// ---------------- K0a: zero degree array ---------------------------------
__global__ void zero_deg_kernel(int n_nodes)
{
    int i = blockIdx.x * blockDim.x + threadIdx.x;
    if (i < n_nodes) g_deg[i] = 0;
}

// ---------------- K0b: normalize edge_index + fused degree histogram -----
// Reference requests int64 but JAX x64-off silently makes int32. Detect the
// layout device-side: for little-endian int64 values in [0, 2^31), the odd
// int32 words of the first 64 entries are all zero.
__global__ void normalize_kernel(const int* __restrict__ raw,
                                 int n_edges, int n_nodes)
{
    __shared__ int is64_sh;
    if (threadIdx.x == 0) {
        int acc = 0;
        for (int i = 0; i < 64; ++i) acc |= raw[2 * i + 1];
        is64_sh = (acc == 0) ? 1 : 0;
    }
    __syncthreads();
    int is64 = is64_sh;
    int e = blockIdx.x * blockDim.x + threadIdx.x;
    if (e >= n_edges) return;
    int s, d;
    if (is64) {
        s = raw[(size_t)e * 2];
        d = raw[((size_t)n_edges + e) * 2];
    } else {
        s = raw[e];
        d = raw[n_edges + e];
    }
    s = min(max(s, 0), n_nodes - 1);
    d = min(max(d, 0), n_nodes - 1);
    g_src[e] = s;
    g_dst[e] = d;
    atomicAdd(&g_deg[d], 1);
}

// ---------------- K1: h = x @ W^T  (f32x2 packed, 128x128 tile) ----------
__global__ __launch_bounds__(256, 2)
void gemm_kernel(const float* __restrict__ x, const float* __restrict__ W,
                 int n_nodes)
{
    __shared__ float xs[32][128];
    __shared__ float ws[32][128];

    const int tid = threadIdx.x;
    const int tc  = tid & 15;
    const int tr  = tid >> 4;
    const int n0  = blockIdx.x * 128;

    u64 acc2[8][4];
#pragma unroll
    for (int i = 0; i < 8; ++i)
#pragma unroll
        for (int j = 0; j < 4; ++j) acc2[i][j] = 0ULL;

    for (int kt = 0; kt < INF_DIM; kt += 32) {
#pragma unroll
        for (int i = 0; i < 4; ++i) {
            int flat = i * 256 + tid;
            int n    = flat & 127;
            int kb   = (flat >> 7) * 4;
            float4 v = make_float4(0.f, 0.f, 0.f, 0.f);
            int gn = n0 + n;
            if (gn < n_nodes)
                v = *(const float4*)&x[(size_t)gn * INF_DIM + kt + kb];
            xs[kb + 0][n] = v.x; xs[kb + 1][n] = v.y;
            xs[kb + 2][n] = v.z; xs[kb + 3][n] = v.w;
            float4 wv = *(const float4*)&W[(size_t)n * INF_DIM + kt + kb];
            ws[kb + 0][n] = wv.x; ws[kb + 1][n] = wv.y;
            ws[kb + 2][n] = wv.z; ws[kb + 3][n] = wv.w;
        }
        __syncthreads();

#pragma unroll 4
        for (int k = 0; k < 32; ++k) {
            float4 a0 = *(const float4*)&xs[k][tr * 4];
            float4 a1 = *(const float4*)&xs[k][tr * 4 + 64];
            float4 b0 = *(const float4*)&ws[k][tc * 4];
            float4 b1 = *(const float4*)&ws[k][tc * 4 + 64];
            u64 bp[4];
            bp[0] = pack2(b0.x, b0.y); bp[1] = pack2(b0.z, b0.w);
            bp[2] = pack2(b1.x, b1.y); bp[3] = pack2(b1.z, b1.w);
            float av[8] = {a0.x, a0.y, a0.z, a0.w, a1.x, a1.y, a1.z, a1.w};
#pragma unroll
            for (int i = 0; i < 8; ++i) {
                u64 aa = pack2(av[i], av[i]);
#pragma unroll
                for (int p = 0; p < 4; ++p)
                    acc2[i][p] = fma2(aa, bp[p], acc2[i][p]);
            }
        }
        __syncthreads();
    }

#pragma unroll
    for (int i = 0; i < 8; ++i) {
        int row = (i < 4) ? (tr * 4 + i) : (tr * 4 + 64 + (i - 4));
        int gn  = n0 + row;
        if (gn < n_nodes) {
            float2 p0 = unpack2(acc2[i][0]);
            float2 p1 = unpack2(acc2[i][1]);
            float2 p2 = unpack2(acc2[i][2]);
            float2 p3 = unpack2(acc2[i][3]);
            float4 o0 = make_float4(p0.x, p0.y, p1.x, p1.y);
            float4 o1 = make_float4(p2.x, p2.y, p3.x, p3.y);
            *(float4*)&g_h[(size_t)gn * OUTF + tc * 4]      = o0;
            *(float4*)&g_h[(size_t)gn * OUTF + tc * 4 + 64] = o1;
        }
    }
}

// ---------------- K2: per-node attention scalars --------------------------
__global__ void scalars_kernel(const float* __restrict__ al,
                               const float* __restrict__ ar, int n_nodes)
{
    int warp = (blockIdx.x * blockDim.x + threadIdx.x) >> 5;
    int lane = threadIdx.x & 31;
    if (warp >= n_nodes) return;
    float4 hv  = *(const float4*)&g_h[(size_t)warp * OUTF + lane * 4];
    float4 alv = *(const float4*)&al[lane * 4];   // [H,D] flat == lane*4
    float4 arv = *(const float4*)&ar[lane * 4];
    float sl = hv.x * alv.x + hv.y * alv.y + hv.z * alv.z + hv.w * alv.w;
    float sr = hv.x * arv.x + hv.y * arv.y + hv.z * arv.z + hv.w * arv.w;
#pragma unroll
    for (int off = 4; off >= 1; off >>= 1) {
        sl += __shfl_xor_sync(0xffffffffu, sl, off);
        sr += __shfl_xor_sync(0xffffffffu, sr, off);
    }
    if ((lane & 7) == 0) {
        g_sl[warp * NHEAD + (lane >> 3)] = sl;
        g_sr[warp * NHEAD + (lane >> 3)] = sr;
    }
}

// ---------------- K4/K5/K6: exclusive scan -------------------------------
__global__ __launch_bounds__(1024)
void scan1_kernel(int n_nodes)
{
    __shared__ int sh[1024];
    int i = blockIdx.x * 1024 + threadIdx.x;
    int v = (i < n_nodes) ? g_deg[i] : 0;
    sh[threadIdx.x] = v;
    __syncthreads();
    int xval = v;
#pragma unroll
    for (int off = 1; off < 1024; off <<= 1) {
        int t = (threadIdx.x >= off) ? sh[threadIdx.x - off] : 0;
        __syncthreads();
        xval += t;
        sh[threadIdx.x] = xval;
        __syncthreads();
    }
    if (i < n_nodes) g_rowptr[i] = xval - v;   // local exclusive
    if (threadIdx.x == 1023) g_bsum[blockIdx.x] = xval;
}

__global__ __launch_bounds__(128)
void scan2_kernel(int nblocks)   // nblocks <= 128
{
    __shared__ int sh[128];
    int t = threadIdx.x;
    int v = (t < nblocks) ? g_bsum[t] : 0;
    sh[t] = v;
    __syncthreads();
    int xval = v;
#pragma unroll
    for (int off = 1; off < 128; off <<= 1) {
        int tv = (t >= off) ? sh[t - off] : 0;
        __syncthreads();
        xval += tv;
        sh[t] = xval;
        __syncthreads();
    }
    if (t < nblocks) g_bsum[t] = xval - v;     // exclusive
}

__global__ void scan3_kernel(int n_nodes, int n_edges)
{
    int i = blockIdx.x * blockDim.x + threadIdx.x;
    if (i < n_nodes) {
        int r = g_rowptr[i] + g_bsum[i >> 10];
        g_rowptr[i] = r;
        g_cursor[i] = r;
    }
    if (i == 0) g_rowptr[n_nodes] = n_edges;
}

// ---------------- K7: edge scatter (src only, dst-ordered CSR) -----------
__global__ void scatter_kernel(int n_edges)
{
    int e = blockIdx.x * blockDim.x + threadIdx.x;
    if (e >= n_edges) return;
    int s = g_src[e];
    int d = g_dst[e];
    int pos = atomicAdd(&g_cursor[d], 1);
    pos = min(max(pos, 0), MAXE - 1);   // defensive
    g_csr_src[pos] = s;
}

// ---------------- K8: warp-per-node aggregation (ee recomputed) ----------
__device__ __forceinline__ float lrelu_exp(float a)
{
    float t = (a > 0.f) ? a : 0.2f * a;
    return __expf(t);
}

__global__ __launch_bounds__(256)
void aggregate_kernel(float* __restrict__ out, int n_nodes, int n_edges)
{
    int warp = (blockIdx.x * blockDim.x + threadIdx.x) >> 5;
    int lane = threadIdx.x & 31;
    if (warp >= n_nodes) return;

    int beg = g_rowptr[warp];
    int end = g_rowptr[warp + 1];
    beg = min(max(beg, 0), n_edges);    // defensive
    end = min(max(end, beg), n_edges);
    int head = lane >> 3;

    float srh = g_sr[(size_t)warp * NHEAD + head];

    const float4* __restrict__ h4 = (const float4*)g_h;

    float4 acc = make_float4(0.f, 0.f, 0.f, 0.f);
    float den = 0.f;

    int j = beg;
    int s = 0; float slv = 0.f;
    if (j < end) {
        s   = g_csr_src[j];
        slv = g_sl[(size_t)s * NHEAD + head];
    }
    while (j < end) {
        float ee = lrelu_exp(slv + srh);
        float4 v = h4[(size_t)s * 32 + lane];
        int jn = j + 1;
        int sn = 0; float sln = 0.f;
        if (jn < end) {
            sn  = g_csr_src[jn];
            sln = g_sl[(size_t)sn * NHEAD + head];
        }
        acc.x += v.x * ee; acc.y += v.y * ee;
        acc.z += v.z * ee; acc.w += v.w * ee;
        den += ee;
        s = sn; slv = sln; j = jn;
    }

    float inv = 1.f / (den + 1e-8f);
    float4 o = make_float4(acc.x * inv, acc.y * inv, acc.z * inv, acc.w * inv);
    *(float4*)&out[(size_t)warp * OUTF + lane * 4] = o;
}

// ---------------- launch ---------------------------------------------------
extern "C" void kernel_launch(void* const* d_in, const int* in_sizes, int n_in,
                              void* d_out, int out_size)
{
    const float* x   = (const float*)d_in[0];
    const int*   ei  = (const int*)d_in[1];     // int32 OR int64 (detected)
    const float* W   = (const float*)d_in[2];
    const float* al  = (const float*)d_in[3];
    const float* ar  = (const float*)d_in[4];
    float* out = (float*)d_out;

    int n_nodes = in_sizes[0] / INF_DIM;
    int n_edges = in_sizes[1] / 2;
    if (n_nodes > MAXN) n_nodes = MAXN;
    if (n_edges > MAXE) n_edges = MAXE;

    // K0a/K0b: zero degrees; normalize + fused histogram
    zero_deg_kernel<<<(n_nodes + 255) / 256, 256>>>(n_nodes);
    normalize_kernel<<<(n_edges + 255) / 256, 256>>>(ei, n_edges, n_nodes);

    // K1: GEMM (f32x2)
    int gemm_blocks = (n_nodes + 127) / 128;
    gemm_kernel<<<gemm_blocks, 256>>>(x, W, n_nodes);

    // K2: node scalars
    int warps_blocks = (n_nodes * 32 + 255) / 256;
    scalars_kernel<<<warps_blocks, 256>>>(al, ar, n_nodes);

    // K4-6: scan -> rowptr, cursor
    int scan_blocks = (n_nodes + 1023) / 1024;
    scan1_kernel<<<scan_blocks, 1024>>>(n_nodes);
    scan2_kernel<<<1, 128>>>(scan_blocks);
    scan3_kernel<<<(n_nodes + 255) / 256, 256>>>(n_nodes, n_edges);

    // K7: scatter edge sources into dst-ordered CSR
    scatter_kernel<<<(n_edges + 255) / 256, 256>>>(n_edges);

    // K8: aggregate
    aggregate_kernel<<<warps_blocks, 256>>>(out, n_nodes, n_edges);
}

// round 5
// speedup vs baseline: 1.2152x; 1.1193x over previous
#include <cuda_runtime.h>
#include <cuda_bf16.h>

// ---------------- problem constants (fixed-shape problem) ----------------
#define MAXN 100000
#define MAXE 1600000
#define INF_DIM 128
#define OUTF 128          // H*D
#define NHEAD 4

typedef unsigned long long u64;

// ---------------- device scratch (no allocations allowed) ----------------
__device__ __align__(16) float  g_h[(size_t)MAXN * OUTF];   // 51.2 MB
__device__ __align__(16) float  g_sl[(size_t)MAXN * NHEAD];
__device__ __align__(16) float  g_sr[(size_t)MAXN * NHEAD];
__device__ int    g_deg[MAXN];
__device__ int    g_rowptr[MAXN + 1];
__device__ int    g_cursor[MAXN];
__device__ int    g_bsum[256];
__device__ int    g_src[MAXE];                    // 6.4 MB
__device__ int    g_dst[MAXE];                    // 6.4 MB
__device__ int    g_csr_src[MAXE];                // 6.4 MB

// ---------------- f32x2 helpers (sm_103a packed fp32 pipe) ----------------
__device__ __forceinline__ u64 pack2(float lo, float hi) {
    u64 r; asm("mov.b64 %0, {%1, %2};" : "=l"(r) : "f"(lo), "f"(hi)); return r;
}
__device__ __forceinline__ u64 fma2(u64 a, u64 b, u64 c) {
    u64 d; asm("fma.rn.f32x2 %0, %1, %2, %3;" : "=l"(d) : "l"(a), "l"(b), "l"(c));
    return d;
}
__device__ __forceinline__ float2 unpack2(u64 v) {
    float2 f; asm("mov.b64 {%0, %1}, %2;" : "=f"(f.x), "=f"(f.y) : "l"(v));
    return f;
}

// ---------------- K0: zero degree array ----------------------------------
__global__ void zero_deg_kernel(int n_nodes)
{
    int i = blockIdx.x * blockDim.x + threadIdx.x;
    if (i < n_nodes) g_deg[i] = 0;
}

// ---------------- K1 (fat): GEMM+scalars epilogue  ||  normalize+hist ----
// Blocks [0, gemm_blocks) compute h = x@W^T with fused attention scalars.
// Blocks [gemm_blocks, ...) normalize edge_index (int32/int64 autodetect)
// and build the in-degree histogram. The two halves are independent.
__global__ __launch_bounds__(256, 2)
void fat_kernel(const float* __restrict__ x, const float* __restrict__ W,
                const float* __restrict__ al, const float* __restrict__ ar,
                const int* __restrict__ raw,
                int n_nodes, int n_edges, int gemm_blocks)
{
    __shared__ float xs[32][128];
    __shared__ float ws[32][128];

    const int tid = threadIdx.x;

    if (blockIdx.x >= gemm_blocks) {
        // ---------------- normalize + histogram part ----------------
        __shared__ int is64_sh;
        if (tid == 0) {
            int acc = 0;
            for (int i = 0; i < 64; ++i) acc |= raw[2 * i + 1];
            is64_sh = (acc == 0) ? 1 : 0;
        }
        __syncthreads();
        int is64 = is64_sh;
        int e = (blockIdx.x - gemm_blocks) * 256 + tid;
        if (e >= n_edges) return;
        int s, d;
        if (is64) {
            s = raw[(size_t)e * 2];
            d = raw[((size_t)n_edges + e) * 2];
        } else {
            s = raw[e];
            d = raw[n_edges + e];
        }
        s = min(max(s, 0), n_nodes - 1);
        d = min(max(d, 0), n_nodes - 1);
        g_src[e] = s;
        g_dst[e] = d;
        atomicAdd(&g_deg[d], 1);
        return;
    }

    // ---------------- GEMM part ----------------
    const int tc  = tid & 15;
    const int tr  = tid >> 4;
    const int n0  = blockIdx.x * 128;

    u64 acc2[8][4];
#pragma unroll
    for (int i = 0; i < 8; ++i)
#pragma unroll
        for (int j = 0; j < 4; ++j) acc2[i][j] = 0ULL;

    for (int kt = 0; kt < INF_DIM; kt += 32) {
#pragma unroll
        for (int i = 0; i < 4; ++i) {
            int flat = i * 256 + tid;
            int n    = flat & 127;
            int kb   = (flat >> 7) * 4;
            float4 v = make_float4(0.f, 0.f, 0.f, 0.f);
            int gn = n0 + n;
            if (gn < n_nodes)
                v = *(const float4*)&x[(size_t)gn * INF_DIM + kt + kb];
            xs[kb + 0][n] = v.x; xs[kb + 1][n] = v.y;
            xs[kb + 2][n] = v.z; xs[kb + 3][n] = v.w;
            float4 wv = *(const float4*)&W[(size_t)n * INF_DIM + kt + kb];
            ws[kb + 0][n] = wv.x; ws[kb + 1][n] = wv.y;
            ws[kb + 2][n] = wv.z; ws[kb + 3][n] = wv.w;
        }
        __syncthreads();

#pragma unroll 4
        for (int k = 0; k < 32; ++k) {
            float4 a0 = *(const float4*)&xs[k][tr * 4];
            float4 a1 = *(const float4*)&xs[k][tr * 4 + 64];
            float4 b0 = *(const float4*)&ws[k][tc * 4];
            float4 b1 = *(const float4*)&ws[k][tc * 4 + 64];
            u64 bp[4];
            bp[0] = pack2(b0.x, b0.y); bp[1] = pack2(b0.z, b0.w);
            bp[2] = pack2(b1.x, b1.y); bp[3] = pack2(b1.z, b1.w);
            float av[8] = {a0.x, a0.y, a0.z, a0.w, a1.x, a1.y, a1.z, a1.w};
#pragma unroll
            for (int i = 0; i < 8; ++i) {
                u64 aa = pack2(av[i], av[i]);
#pragma unroll
                for (int p = 0; p < 4; ++p)
                    acc2[i][p] = fma2(aa, bp[p], acc2[i][p]);
            }
        }
        __syncthreads();
    }

    // Epilogue: store h AND fused attention scalars.
    // Thread owns cols [tc*4, tc*4+4) (head A = tc>>3) and
    // [tc*4+64, tc*4+68) (head B = (tc>>3)+2). Within-head dim base:
    const int headA = tc >> 3;
    const int dbase = (tc & 7) * 4;
    float4 alA = *(const float4*)&al[headA * 32 + dbase];
    float4 alB = *(const float4*)&al[(headA + 2) * 32 + dbase];
    float4 arA = *(const float4*)&ar[headA * 32 + dbase];
    float4 arB = *(const float4*)&ar[(headA + 2) * 32 + dbase];

#pragma unroll
    for (int i = 0; i < 8; ++i) {
        int row = (i < 4) ? (tr * 4 + i) : (tr * 4 + 64 + (i - 4));
        int gn  = n0 + row;
        float2 p0 = unpack2(acc2[i][0]);
        float2 p1 = unpack2(acc2[i][1]);
        float2 p2 = unpack2(acc2[i][2]);
        float2 p3 = unpack2(acc2[i][3]);
        float f0 = p0.x, f1 = p0.y, f2 = p1.x, f3 = p1.y;
        float f4 = p2.x, f5 = p2.y, f6 = p3.x, f7 = p3.y;

        if (gn < n_nodes) {
            *(float4*)&g_h[(size_t)gn * OUTF + tc * 4]      = make_float4(f0, f1, f2, f3);
            *(float4*)&g_h[(size_t)gn * OUTF + tc * 4 + 64] = make_float4(f4, f5, f6, f7);
        }

        float lA = f0 * alA.x + f1 * alA.y + f2 * alA.z + f3 * alA.w;
        float lB = f4 * alB.x + f5 * alB.y + f6 * alB.z + f7 * alB.w;
        float rA = f0 * arA.x + f1 * arA.y + f2 * arA.z + f3 * arA.w;
        float rB = f4 * arB.x + f5 * arB.y + f6 * arB.z + f7 * arB.w;
        // reduce over the 8 lanes sharing (row, head): lane bits 0..2 == tc%8
#pragma unroll
        for (int off = 1; off <= 4; off <<= 1) {
            lA += __shfl_xor_sync(0xffffffffu, lA, off);
            lB += __shfl_xor_sync(0xffffffffu, lB, off);
            rA += __shfl_xor_sync(0xffffffffu, rA, off);
            rB += __shfl_xor_sync(0xffffffffu, rB, off);
        }
        if ((tc & 7) == 0 && gn < n_nodes) {
            g_sl[(size_t)gn * NHEAD + headA]     = lA;
            g_sl[(size_t)gn * NHEAD + headA + 2] = lB;
            g_sr[(size_t)gn * NHEAD + headA]     = rA;
            g_sr[(size_t)gn * NHEAD + headA + 2] = rB;
        }
    }
}

// ---------------- K4/K5/K6: exclusive scan -------------------------------
__global__ __launch_bounds__(1024)
void scan1_kernel(int n_nodes)
{
    __shared__ int sh[1024];
    int i = blockIdx.x * 1024 + threadIdx.x;
    int v = (i < n_nodes) ? g_deg[i] : 0;
    sh[threadIdx.x] = v;
    __syncthreads();
    int xval = v;
#pragma unroll
    for (int off = 1; off < 1024; off <<= 1) {
        int t = (threadIdx.x >= off) ? sh[threadIdx.x - off] : 0;
        __syncthreads();
        xval += t;
        sh[threadIdx.x] = xval;
        __syncthreads();
    }
    if (i < n_nodes) g_rowptr[i] = xval - v;   // local exclusive
    if (threadIdx.x == 1023) g_bsum[blockIdx.x] = xval;
}

__global__ __launch_bounds__(128)
void scan2_kernel(int nblocks)   // nblocks <= 128
{
    __shared__ int sh[128];
    int t = threadIdx.x;
    int v = (t < nblocks) ? g_bsum[t] : 0;
    sh[t] = v;
    __syncthreads();
    int xval = v;
#pragma unroll
    for (int off = 1; off < 128; off <<= 1) {
        int tv = (t >= off) ? sh[t - off] : 0;
        __syncthreads();
        xval += tv;
        sh[t] = xval;
        __syncthreads();
    }
    if (t < nblocks) g_bsum[t] = xval - v;     // exclusive
}

__global__ void scan3_kernel(int n_nodes, int n_edges)
{
    int i = blockIdx.x * blockDim.x + threadIdx.x;
    if (i < n_nodes) {
        int r = g_rowptr[i] + g_bsum[i >> 10];
        g_rowptr[i] = r;
        g_cursor[i] = r;
    }
    if (i == 0) g_rowptr[n_nodes] = n_edges;
}

// ---------------- K7: edge scatter (src only, dst-ordered CSR) -----------
__global__ void scatter_kernel(int n_edges)
{
    int e = blockIdx.x * blockDim.x + threadIdx.x;
    if (e >= n_edges) return;
    int s = g_src[e];
    int d = g_dst[e];
    int pos = atomicAdd(&g_cursor[d], 1);
    pos = min(max(pos, 0), MAXE - 1);   // defensive
    g_csr_src[pos] = s;
}

// ---------------- K8: warp-per-node aggregation (unroll x4) --------------
__device__ __forceinline__ float lrelu_exp(float a)
{
    float t = (a > 0.f) ? a : 0.2f * a;
    return __expf(t);
}

__global__ __launch_bounds__(256)
void aggregate_kernel(float* __restrict__ out, int n_nodes, int n_edges)
{
    int warp = (blockIdx.x * blockDim.x + threadIdx.x) >> 5;
    int lane = threadIdx.x & 31;
    if (warp >= n_nodes) return;

    int beg = g_rowptr[warp];
    int end = g_rowptr[warp + 1];
    beg = min(max(beg, 0), n_edges);    // defensive
    end = min(max(end, beg), n_edges);
    int head = lane >> 3;

    float srh = g_sr[(size_t)warp * NHEAD + head];

    const float4* __restrict__ h4 = (const float4*)g_h;
    const int*    __restrict__ csr = g_csr_src;

    float4 acc = make_float4(0.f, 0.f, 0.f, 0.f);
    float den = 0.f;

    int j = beg;
    // unroll x4: 4 independent gather chains in flight
    for (; j + 3 < end; j += 4) {
        int s0 = csr[j], s1 = csr[j + 1], s2 = csr[j + 2], s3 = csr[j + 3];
        float w0 = g_sl[(size_t)s0 * NHEAD + head];
        float w1 = g_sl[(size_t)s1 * NHEAD + head];
        float w2 = g_sl[(size_t)s2 * NHEAD + head];
        float w3 = g_sl[(size_t)s3 * NHEAD + head];
        float4 v0 = h4[(size_t)s0 * 32 + lane];
        float4 v1 = h4[(size_t)s1 * 32 + lane];
        float4 v2 = h4[(size_t)s2 * 32 + lane];
        float4 v3 = h4[(size_t)s3 * 32 + lane];
        float e0 = lrelu_exp(w0 + srh);
        float e1 = lrelu_exp(w1 + srh);
        float e2 = lrelu_exp(w2 + srh);
        float e3 = lrelu_exp(w3 + srh);
        acc.x += v0.x * e0 + v1.x * e1 + v2.x * e2 + v3.x * e3;
        acc.y += v0.y * e0 + v1.y * e1 + v2.y * e2 + v3.y * e3;
        acc.z += v0.z * e0 + v1.z * e1 + v2.z * e2 + v3.z * e3;
        acc.w += v0.w * e0 + v1.w * e1 + v2.w * e2 + v3.w * e3;
        den   += e0 + e1 + e2 + e3;
    }
    for (; j < end; ++j) {
        int s = csr[j];
        float ee = lrelu_exp(g_sl[(size_t)s * NHEAD + head] + srh);
        float4 v = h4[(size_t)s * 32 + lane];
        acc.x += v.x * ee; acc.y += v.y * ee;
        acc.z += v.z * ee; acc.w += v.w * ee;
        den += ee;
    }

    float inv = 1.f / (den + 1e-8f);
    float4 o = make_float4(acc.x * inv, acc.y * inv, acc.z * inv, acc.w * inv);
    *(float4*)&out[(size_t)warp * OUTF + lane * 4] = o;
}

// ---------------- launch ---------------------------------------------------
extern "C" void kernel_launch(void* const* d_in, const int* in_sizes, int n_in,
                              void* d_out, int out_size)
{
    const float* x   = (const float*)d_in[0];
    const int*   ei  = (const int*)d_in[1];     // int32 OR int64 (detected)
    const float* W   = (const float*)d_in[2];
    const float* al  = (const float*)d_in[3];
    const float* ar  = (const float*)d_in[4];
    float* out = (float*)d_out;

    int n_nodes = in_sizes[0] / INF_DIM;
    int n_edges = in_sizes[1] / 2;
    if (n_nodes > MAXN) n_nodes = MAXN;
    if (n_edges > MAXE) n_edges = MAXE;

    // K0: zero degrees
    zero_deg_kernel<<<(n_nodes + 255) / 256, 256>>>(n_nodes);

    // K1: fat kernel — GEMM(+scalars) || normalize(+hist)
    int gemm_blocks = (n_nodes + 127) / 128;
    int norm_blocks = (n_edges + 255) / 256;
    fat_kernel<<<gemm_blocks + norm_blocks, 256>>>(x, W, al, ar, ei,
                                                   n_nodes, n_edges, gemm_blocks);

    // K4-6: scan -> rowptr, cursor
    int scan_blocks = (n_nodes + 1023) / 1024;
    scan1_kernel<<<scan_blocks, 1024>>>(n_nodes);
    scan2_kernel<<<1, 128>>>(scan_blocks);
    scan3_kernel<<<(n_nodes + 255) / 256, 256>>>(n_nodes, n_edges);

    // K7: scatter edge sources into dst-ordered CSR
    scatter_kernel<<<(n_edges + 255) / 256, 256>>>(n_edges);

    // K8: aggregate
    int warps_blocks = (n_nodes * 32 + 255) / 256;
    aggregate_kernel<<<warps_blocks, 256>>>(out, n_nodes, n_edges);
}

// round 6
// speedup vs baseline: 1.2502x; 1.0288x over previous
#include <cuda_runtime.h>
#include <cuda_bf16.h>

// ---------------- problem constants (fixed-shape problem) ----------------
#define MAXN 100000
#define MAXE 1600000
#define INF_DIM 128
#define OUTF 128          // H*D
#define NHEAD 4

typedef unsigned long long u64;

// ---------------- device scratch (no allocations allowed) ----------------
// NOTE: g_deg relies on a zero-state invariant: device globals are
// zero-initialized at load, and scan1 re-zeros each entry after consuming it,
// so every kernel_launch invocation (incl. graph replays) sees g_deg == 0.
__device__ __align__(16) float  g_h[(size_t)MAXN * OUTF];   // 51.2 MB
__device__ __align__(16) float  g_sl[(size_t)MAXN * NHEAD];
__device__ __align__(16) float  g_sr[(size_t)MAXN * NHEAD];
__device__ int    g_deg[MAXN];
__device__ int    g_rowptr[MAXN + 1];
__device__ int    g_cursor[MAXN];
__device__ int    g_bsum[128];
__device__ int    g_src[MAXE];                    // 6.4 MB
__device__ int    g_dst[MAXE];                    // 6.4 MB
__device__ int    g_csr_src[MAXE];                // 6.4 MB

// ---------------- f32x2 helpers (sm_103a packed fp32 pipe) ----------------
__device__ __forceinline__ u64 pack2(float lo, float hi) {
    u64 r; asm("mov.b64 %0, {%1, %2};" : "=l"(r) : "f"(lo), "f"(hi)); return r;
}
__device__ __forceinline__ u64 fma2(u64 a, u64 b, u64 c) {
    u64 d; asm("fma.rn.f32x2 %0, %1, %2, %3;" : "=l"(d) : "l"(a), "l"(b), "l"(c));
    return d;
}
__device__ __forceinline__ float2 unpack2(u64 v) {
    float2 f; asm("mov.b64 {%0, %1}, %2;" : "=f"(f.x), "=f"(f.y) : "l"(v));
    return f;
}

// ---------------- K1: normalize edge_index + degree histogram ------------
// int64-vs-int32 autodetect: for LE int64 values < 2^31 the odd words of the
// first 64 entries are all zero; for int32 data that's ~impossible.
__global__ void normalize_kernel(const int* __restrict__ raw,
                                 int n_edges, int n_nodes)
{
    __shared__ int is64_sh;
    if (threadIdx.x == 0) {
        int acc = 0;
        for (int i = 0; i < 64; ++i) acc |= raw[2 * i + 1];
        is64_sh = (acc == 0) ? 1 : 0;
    }
    __syncthreads();
    int is64 = is64_sh;
    int e = blockIdx.x * blockDim.x + threadIdx.x;
    if (e >= n_edges) return;
    int s, d;
    if (is64) {
        s = raw[(size_t)e * 2];
        d = raw[((size_t)n_edges + e) * 2];
    } else {
        s = raw[e];
        d = raw[n_edges + e];
    }
    s = min(max(s, 0), n_nodes - 1);
    d = min(max(d, 0), n_nodes - 1);
    g_src[e] = s;
    g_dst[e] = d;
    atomicAdd(&g_deg[d], 1);
}

// ---------------- K2: scan part 1 (per-1024-chunk) + deg re-zero ----------
__global__ __launch_bounds__(1024)
void scan1_kernel(int n_nodes)
{
    __shared__ int sh[1024];
    int i = blockIdx.x * 1024 + threadIdx.x;
    int v = 0;
    if (i < n_nodes) {
        v = g_deg[i];
        g_deg[i] = 0;            // restore zero-state invariant for next call
    }
    sh[threadIdx.x] = v;
    __syncthreads();
    int xval = v;
#pragma unroll
    for (int off = 1; off < 1024; off <<= 1) {
        int t = (threadIdx.x >= off) ? sh[threadIdx.x - off] : 0;
        __syncthreads();
        xval += t;
        sh[threadIdx.x] = xval;
        __syncthreads();
    }
    if (i < n_nodes) g_rowptr[i] = xval - v;   // local exclusive
    if (threadIdx.x == 1023) g_bsum[blockIdx.x] = xval;
}

// ---------------- K3: scan part 2 (embedded bsum scan) + cursor init ------
__global__ __launch_bounds__(256)
void scan3_kernel(int n_nodes, int n_edges, int nblocks)  // nblocks <= 128
{
    __shared__ int sb[128];
    int t = threadIdx.x;
    if (t < 128) sb[t] = (t < nblocks) ? g_bsum[t] : 0;
    __syncthreads();
    // exclusive scan of 128 slots (Hillis-Steele), done redundantly per block
    if (t < 128) {
        int v = sb[t];
        int xval = v;
#pragma unroll
        for (int off = 1; off < 128; off <<= 1) {
            int tv = (t >= off) ? sb[t - off] : 0;
            __syncthreads();
            xval += tv;
            sb[t] = xval;
            __syncthreads();
        }
        sb[t] = xval - v;   // exclusive
    } else {
#pragma unroll
        for (int off = 1; off < 128; off <<= 1) { __syncthreads(); __syncthreads(); }
    }
    __syncthreads();

    int i = blockIdx.x * blockDim.x + t;
    if (i < n_nodes) {
        int r = g_rowptr[i] + sb[i >> 10];
        g_rowptr[i] = r;
        g_cursor[i] = r;
    }
    if (i == 0) g_rowptr[n_nodes] = n_edges;
}

// ---------------- K4 (fat): GEMM+scalars  ||  scatter ---------------------
// Blocks [0, gemm_blocks): h = x@W^T with fused attention scalars.
// Blocks [gemm_blocks, ...): scatter edge srcs into dst-ordered CSR.
// The two halves are independent (scatter never touches h/sl/sr).
__global__ __launch_bounds__(256, 2)
void fat_kernel(const float* __restrict__ x, const float* __restrict__ W,
                const float* __restrict__ al, const float* __restrict__ ar,
                int n_nodes, int n_edges, int gemm_blocks)
{
    __shared__ float xs[32][128];
    __shared__ float ws[32][128];

    const int tid = threadIdx.x;

    if (blockIdx.x >= gemm_blocks) {
        // ---------------- scatter part ----------------
        int e = (blockIdx.x - gemm_blocks) * 256 + tid;
        if (e >= n_edges) return;
        int s = g_src[e];
        int d = g_dst[e];
        int pos = atomicAdd(&g_cursor[d], 1);
        pos = min(max(pos, 0), MAXE - 1);   // defensive
        g_csr_src[pos] = s;
        return;
    }

    // ---------------- GEMM part ----------------
    const int tc  = tid & 15;
    const int tr  = tid >> 4;
    const int n0  = blockIdx.x * 128;

    u64 acc2[8][4];
#pragma unroll
    for (int i = 0; i < 8; ++i)
#pragma unroll
        for (int j = 0; j < 4; ++j) acc2[i][j] = 0ULL;

    for (int kt = 0; kt < INF_DIM; kt += 32) {
#pragma unroll
        for (int i = 0; i < 4; ++i) {
            int flat = i * 256 + tid;
            int n    = flat & 127;
            int kb   = (flat >> 7) * 4;
            float4 v = make_float4(0.f, 0.f, 0.f, 0.f);
            int gn = n0 + n;
            if (gn < n_nodes)
                v = *(const float4*)&x[(size_t)gn * INF_DIM + kt + kb];
            xs[kb + 0][n] = v.x; xs[kb + 1][n] = v.y;
            xs[kb + 2][n] = v.z; xs[kb + 3][n] = v.w;
            float4 wv = *(const float4*)&W[(size_t)n * INF_DIM + kt + kb];
            ws[kb + 0][n] = wv.x; ws[kb + 1][n] = wv.y;
            ws[kb + 2][n] = wv.z; ws[kb + 3][n] = wv.w;
        }
        __syncthreads();

#pragma unroll 4
        for (int k = 0; k < 32; ++k) {
            float4 a0 = *(const float4*)&xs[k][tr * 4];
            float4 a1 = *(const float4*)&xs[k][tr * 4 + 64];
            float4 b0 = *(const float4*)&ws[k][tc * 4];
            float4 b1 = *(const float4*)&ws[k][tc * 4 + 64];
            u64 bp[4];
            bp[0] = pack2(b0.x, b0.y); bp[1] = pack2(b0.z, b0.w);
            bp[2] = pack2(b1.x, b1.y); bp[3] = pack2(b1.z, b1.w);
            float av[8] = {a0.x, a0.y, a0.z, a0.w, a1.x, a1.y, a1.z, a1.w};
#pragma unroll
            for (int i = 0; i < 8; ++i) {
                u64 aa = pack2(av[i], av[i]);
#pragma unroll
                for (int p = 0; p < 4; ++p)
                    acc2[i][p] = fma2(aa, bp[p], acc2[i][p]);
            }
        }
        __syncthreads();
    }

    // Epilogue: store h AND fused attention scalars.
    const int headA = tc >> 3;
    const int dbase = (tc & 7) * 4;
    float4 alA = *(const float4*)&al[headA * 32 + dbase];
    float4 alB = *(const float4*)&al[(headA + 2) * 32 + dbase];
    float4 arA = *(const float4*)&ar[headA * 32 + dbase];
    float4 arB = *(const float4*)&ar[(headA + 2) * 32 + dbase];

#pragma unroll
    for (int i = 0; i < 8; ++i) {
        int row = (i < 4) ? (tr * 4 + i) : (tr * 4 + 64 + (i - 4));
        int gn  = n0 + row;
        float2 p0 = unpack2(acc2[i][0]);
        float2 p1 = unpack2(acc2[i][1]);
        float2 p2 = unpack2(acc2[i][2]);
        float2 p3 = unpack2(acc2[i][3]);
        float f0 = p0.x, f1 = p0.y, f2 = p1.x, f3 = p1.y;
        float f4 = p2.x, f5 = p2.y, f6 = p3.x, f7 = p3.y;

        if (gn < n_nodes) {
            *(float4*)&g_h[(size_t)gn * OUTF + tc * 4]      = make_float4(f0, f1, f2, f3);
            *(float4*)&g_h[(size_t)gn * OUTF + tc * 4 + 64] = make_float4(f4, f5, f6, f7);
        }

        float lA = f0 * alA.x + f1 * alA.y + f2 * alA.z + f3 * alA.w;
        float lB = f4 * alB.x + f5 * alB.y + f6 * alB.z + f7 * alB.w;
        float rA = f0 * arA.x + f1 * arA.y + f2 * arA.z + f3 * arA.w;
        float rB = f4 * arB.x + f5 * arB.y + f6 * arB.z + f7 * arB.w;
#pragma unroll
        for (int off = 1; off <= 4; off <<= 1) {
            lA += __shfl_xor_sync(0xffffffffu, lA, off);
            lB += __shfl_xor_sync(0xffffffffu, lB, off);
            rA += __shfl_xor_sync(0xffffffffu, rA, off);
            rB += __shfl_xor_sync(0xffffffffu, rB, off);
        }
        if ((tc & 7) == 0 && gn < n_nodes) {
            g_sl[(size_t)gn * NHEAD + headA]     = lA;
            g_sl[(size_t)gn * NHEAD + headA + 2] = lB;
            g_sr[(size_t)gn * NHEAD + headA]     = rA;
            g_sr[(size_t)gn * NHEAD + headA + 2] = rB;
        }
    }
}

// ---------------- K5: warp-per-node aggregation (unroll x4) --------------
__device__ __forceinline__ float lrelu_exp(float a)
{
    float t = (a > 0.f) ? a : 0.2f * a;
    return __expf(t);
}

__global__ __launch_bounds__(256)
void aggregate_kernel(float* __restrict__ out, int n_nodes, int n_edges)
{
    int warp = (blockIdx.x * blockDim.x + threadIdx.x) >> 5;
    int lane = threadIdx.x & 31;
    if (warp >= n_nodes) return;

    int beg = g_rowptr[warp];
    int end = g_rowptr[warp + 1];
    beg = min(max(beg, 0), n_edges);    // defensive
    end = min(max(end, beg), n_edges);
    int head = lane >> 3;

    float srh = g_sr[(size_t)warp * NHEAD + head];

    const float4* __restrict__ h4 = (const float4*)g_h;
    const int*    __restrict__ csr = g_csr_src;

    float4 acc = make_float4(0.f, 0.f, 0.f, 0.f);
    float den = 0.f;

    int j = beg;
    for (; j + 3 < end; j += 4) {
        int s0 = csr[j], s1 = csr[j + 1], s2 = csr[j + 2], s3 = csr[j + 3];
        float w0 = g_sl[(size_t)s0 * NHEAD + head];
        float w1 = g_sl[(size_t)s1 * NHEAD + head];
        float w2 = g_sl[(size_t)s2 * NHEAD + head];
        float w3 = g_sl[(size_t)s3 * NHEAD + head];
        float4 v0 = h4[(size_t)s0 * 32 + lane];
        float4 v1 = h4[(size_t)s1 * 32 + lane];
        float4 v2 = h4[(size_t)s2 * 32 + lane];
        float4 v3 = h4[(size_t)s3 * 32 + lane];
        float e0 = lrelu_exp(w0 + srh);
        float e1 = lrelu_exp(w1 + srh);
        float e2 = lrelu_exp(w2 + srh);
        float e3 = lrelu_exp(w3 + srh);
        acc.x += v0.x * e0 + v1.x * e1 + v2.x * e2 + v3.x * e3;
        acc.y += v0.y * e0 + v1.y * e1 + v2.y * e2 + v3.y * e3;
        acc.z += v0.z * e0 + v1.z * e1 + v2.z * e2 + v3.z * e3;
        acc.w += v0.w * e0 + v1.w * e1 + v2.w * e2 + v3.w * e3;
        den   += e0 + e1 + e2 + e3;
    }
    for (; j < end; ++j) {
        int s = csr[j];
        float ee = lrelu_exp(g_sl[(size_t)s * NHEAD + head] + srh);
        float4 v = h4[(size_t)s * 32 + lane];
        acc.x += v.x * ee; acc.y += v.y * ee;
        acc.z += v.z * ee; acc.w += v.w * ee;
        den += ee;
    }

    float inv = 1.f / (den + 1e-8f);
    float4 o = make_float4(acc.x * inv, acc.y * inv, acc.z * inv, acc.w * inv);
    *(float4*)&out[(size_t)warp * OUTF + lane * 4] = o;
}

// ---------------- launch ---------------------------------------------------
extern "C" void kernel_launch(void* const* d_in, const int* in_sizes, int n_in,
                              void* d_out, int out_size)
{
    const float* x   = (const float*)d_in[0];
    const int*   ei  = (const int*)d_in[1];     // int32 OR int64 (detected)
    const float* W   = (const float*)d_in[2];
    const float* al  = (const float*)d_in[3];
    const float* ar  = (const float*)d_in[4];
    float* out = (float*)d_out;

    int n_nodes = in_sizes[0] / INF_DIM;
    int n_edges = in_sizes[1] / 2;
    if (n_nodes > MAXN) n_nodes = MAXN;
    if (n_edges > MAXE) n_edges = MAXE;

    // K1: normalize + degree histogram (g_deg is zero by invariant)
    normalize_kernel<<<(n_edges + 255) / 256, 256>>>(ei, n_edges, n_nodes);

    // K2/K3: scan -> rowptr, cursor (scan1 re-zeros g_deg)
    int scan_blocks = (n_nodes + 1023) / 1024;
    scan1_kernel<<<scan_blocks, 1024>>>(n_nodes);
    scan3_kernel<<<(n_nodes + 255) / 256, 256>>>(n_nodes, n_edges, scan_blocks);

    // K4: fat kernel — GEMM(+scalars) || scatter
    int gemm_blocks = (n_nodes + 127) / 128;
    int scat_blocks = (n_edges + 255) / 256;
    fat_kernel<<<gemm_blocks + scat_blocks, 256>>>(x, W, al, ar,
                                                   n_nodes, n_edges, gemm_blocks);

    // K5: aggregate
    int warps_blocks = (n_nodes * 32 + 255) / 256;
    aggregate_kernel<<<warps_blocks, 256>>>(out, n_nodes, n_edges);
}

// round 7
// speedup vs baseline: 1.2764x; 1.0210x over previous
#include <cuda_runtime.h>
#include <cuda_fp16.h>

// ---------------- problem constants (fixed-shape problem) ----------------
#define MAXN 100000
#define MAXE 1600000
#define INF_DIM 128
#define OUTF 128          // H*D
#define NHEAD 4

typedef unsigned long long u64;

// ---------------- device scratch (no allocations allowed) ----------------
// g_deg zero-state invariant: zero-initialized at load; scan1 re-zeros each
// entry after consuming it, so every launch (incl. graph replays) sees 0.
__device__ __align__(16) __half2 g_h2[(size_t)MAXN * 64];   // 25.6 MB (fp16 h)
__device__ __align__(16) float   g_sl[(size_t)MAXN * NHEAD];
__device__ __align__(16) float   g_sr[(size_t)MAXN * NHEAD];
__device__ int    g_deg[MAXN];
__device__ int    g_rowptr[MAXN + 1];
__device__ int    g_cursor[MAXN];
__device__ int    g_bsum[128];
__device__ int    g_src[MAXE];                    // 6.4 MB
__device__ int    g_dst[MAXE];                    // 6.4 MB
__device__ int    g_csr_src[MAXE];                // 6.4 MB

// ---------------- f32x2 helpers (sm_103a packed fp32 pipe) ----------------
__device__ __forceinline__ u64 pack2(float lo, float hi) {
    u64 r; asm("mov.b64 %0, {%1, %2};" : "=l"(r) : "f"(lo), "f"(hi)); return r;
}
__device__ __forceinline__ u64 fma2(u64 a, u64 b, u64 c) {
    u64 d; asm("fma.rn.f32x2 %0, %1, %2, %3;" : "=l"(d) : "l"(a), "l"(b), "l"(c));
    return d;
}
__device__ __forceinline__ float2 unpack2(u64 v) {
    float2 f; asm("mov.b64 {%0, %1}, %2;" : "=f"(f.x), "=f"(f.y) : "l"(v));
    return f;
}

// ---------------- K1: normalize edge_index + degree histogram ------------
__global__ void normalize_kernel(const int* __restrict__ raw,
                                 int n_edges, int n_nodes)
{
    __shared__ int is64_sh;
    if (threadIdx.x == 0) {
        int acc = 0;
        for (int i = 0; i < 64; ++i) acc |= raw[2 * i + 1];
        is64_sh = (acc == 0) ? 1 : 0;
    }
    __syncthreads();
    int is64 = is64_sh;
    int e = blockIdx.x * blockDim.x + threadIdx.x;
    if (e >= n_edges) return;
    int s, d;
    if (is64) {
        s = raw[(size_t)e * 2];
        d = raw[((size_t)n_edges + e) * 2];
    } else {
        s = raw[e];
        d = raw[n_edges + e];
    }
    s = min(max(s, 0), n_nodes - 1);
    d = min(max(d, 0), n_nodes - 1);
    g_src[e] = s;
    g_dst[e] = d;
    atomicAdd(&g_deg[d], 1);
}

// ---------------- K2: scan part 1 (per-1024-chunk) + deg re-zero ----------
__global__ __launch_bounds__(1024)
void scan1_kernel(int n_nodes)
{
    __shared__ int sh[1024];
    int i = blockIdx.x * 1024 + threadIdx.x;
    int v = 0;
    if (i < n_nodes) {
        v = g_deg[i];
        g_deg[i] = 0;
    }
    sh[threadIdx.x] = v;
    __syncthreads();
    int xval = v;
#pragma unroll
    for (int off = 1; off < 1024; off <<= 1) {
        int t = (threadIdx.x >= off) ? sh[threadIdx.x - off] : 0;
        __syncthreads();
        xval += t;
        sh[threadIdx.x] = xval;
        __syncthreads();
    }
    if (i < n_nodes) g_rowptr[i] = xval - v;
    if (threadIdx.x == 1023) g_bsum[blockIdx.x] = xval;
}

// ---------------- K3: scan part 2 (embedded bsum scan) + cursor init ------
__global__ __launch_bounds__(256)
void scan3_kernel(int n_nodes, int n_edges, int nblocks)  // nblocks <= 128
{
    __shared__ int sb[128];
    int t = threadIdx.x;
    if (t < 128) sb[t] = (t < nblocks) ? g_bsum[t] : 0;
    __syncthreads();
    if (t < 128) {
        int v = sb[t];
        int xval = v;
#pragma unroll
        for (int off = 1; off < 128; off <<= 1) {
            int tv = (t >= off) ? sb[t - off] : 0;
            __syncthreads();
            xval += tv;
            sb[t] = xval;
            __syncthreads();
        }
        sb[t] = xval - v;
    } else {
#pragma unroll
        for (int off = 1; off < 128; off <<= 1) { __syncthreads(); __syncthreads(); }
    }
    __syncthreads();

    int i = blockIdx.x * blockDim.x + t;
    if (i < n_nodes) {
        int r = g_rowptr[i] + sb[i >> 10];
        g_rowptr[i] = r;
        g_cursor[i] = r;
    }
    if (i == 0) g_rowptr[n_nodes] = n_edges;
}

// ---------------- K4 (fat): GEMM+scalars  ||  scatter ---------------------
__global__ __launch_bounds__(256, 2)
void fat_kernel(const float* __restrict__ x, const float* __restrict__ W,
                const float* __restrict__ al, const float* __restrict__ ar,
                int n_nodes, int n_edges, int gemm_blocks)
{
    __shared__ float xs[32][128];
    __shared__ float ws[32][128];

    const int tid = threadIdx.x;

    if (blockIdx.x >= gemm_blocks) {
        // ---------------- scatter part ----------------
        int e = (blockIdx.x - gemm_blocks) * 256 + tid;
        if (e >= n_edges) return;
        int s = g_src[e];
        int d = g_dst[e];
        int pos = atomicAdd(&g_cursor[d], 1);
        pos = min(max(pos, 0), MAXE - 1);
        g_csr_src[pos] = s;
        return;
    }

    // ---------------- GEMM part ----------------
    const int tc  = tid & 15;
    const int tr  = tid >> 4;
    const int n0  = blockIdx.x * 128;

    u64 acc2[8][4];
#pragma unroll
    for (int i = 0; i < 8; ++i)
#pragma unroll
        for (int j = 0; j < 4; ++j) acc2[i][j] = 0ULL;

    for (int kt = 0; kt < INF_DIM; kt += 32) {
#pragma unroll
        for (int i = 0; i < 4; ++i) {
            int flat = i * 256 + tid;
            int n    = flat & 127;
            int kb   = (flat >> 7) * 4;
            float4 v = make_float4(0.f, 0.f, 0.f, 0.f);
            int gn = n0 + n;
            if (gn < n_nodes)
                v = *(const float4*)&x[(size_t)gn * INF_DIM + kt + kb];
            xs[kb + 0][n] = v.x; xs[kb + 1][n] = v.y;
            xs[kb + 2][n] = v.z; xs[kb + 3][n] = v.w;
            float4 wv = *(const float4*)&W[(size_t)n * INF_DIM + kt + kb];
            ws[kb + 0][n] = wv.x; ws[kb + 1][n] = wv.y;
            ws[kb + 2][n] = wv.z; ws[kb + 3][n] = wv.w;
        }
        __syncthreads();

#pragma unroll 8
        for (int k = 0; k < 32; ++k) {
            float4 a0 = *(const float4*)&xs[k][tr * 4];
            float4 a1 = *(const float4*)&xs[k][tr * 4 + 64];
            float4 b0 = *(const float4*)&ws[k][tc * 4];
            float4 b1 = *(const float4*)&ws[k][tc * 4 + 64];
            u64 bp[4];
            bp[0] = pack2(b0.x, b0.y); bp[1] = pack2(b0.z, b0.w);
            bp[2] = pack2(b1.x, b1.y); bp[3] = pack2(b1.z, b1.w);
            float av[8] = {a0.x, a0.y, a0.z, a0.w, a1.x, a1.y, a1.z, a1.w};
#pragma unroll
            for (int i = 0; i < 8; ++i) {
                u64 aa = pack2(av[i], av[i]);
#pragma unroll
                for (int p = 0; p < 4; ++p)
                    acc2[i][p] = fma2(aa, bp[p], acc2[i][p]);
            }
        }
        __syncthreads();
    }

    // Epilogue: store h (fp16) AND fused attention scalars (fp32).
    const int headA = tc >> 3;
    const int dbase = (tc & 7) * 4;
    float4 alA = *(const float4*)&al[headA * 32 + dbase];
    float4 alB = *(const float4*)&al[(headA + 2) * 32 + dbase];
    float4 arA = *(const float4*)&ar[headA * 32 + dbase];
    float4 arB = *(const float4*)&ar[(headA + 2) * 32 + dbase];

#pragma unroll
    for (int i = 0; i < 8; ++i) {
        int row = (i < 4) ? (tr * 4 + i) : (tr * 4 + 64 + (i - 4));
        int gn  = n0 + row;
        float2 p0 = unpack2(acc2[i][0]);
        float2 p1 = unpack2(acc2[i][1]);
        float2 p2 = unpack2(acc2[i][2]);
        float2 p3 = unpack2(acc2[i][3]);
        float f0 = p0.x, f1 = p0.y, f2 = p1.x, f3 = p1.y;
        float f4 = p2.x, f5 = p2.y, f6 = p3.x, f7 = p3.y;

        if (gn < n_nodes) {
            __half2 h01 = __floats2half2_rn(f0, f1);
            __half2 h23 = __floats2half2_rn(f2, f3);
            __half2 h45 = __floats2half2_rn(f4, f5);
            __half2 h67 = __floats2half2_rn(f6, f7);
            __half2* dst0 = &g_h2[(size_t)gn * 64 + tc * 2];
            __half2* dst1 = &g_h2[(size_t)gn * 64 + 32 + tc * 2];
            dst0[0] = h01; dst0[1] = h23;
            dst1[0] = h45; dst1[1] = h67;
        }

        float lA = f0 * alA.x + f1 * alA.y + f2 * alA.z + f3 * alA.w;
        float lB = f4 * alB.x + f5 * alB.y + f6 * alB.z + f7 * alB.w;
        float rA = f0 * arA.x + f1 * arA.y + f2 * arA.z + f3 * arA.w;
        float rB = f4 * arB.x + f5 * arB.y + f6 * arB.z + f7 * arB.w;
#pragma unroll
        for (int off = 1; off <= 4; off <<= 1) {
            lA += __shfl_xor_sync(0xffffffffu, lA, off);
            lB += __shfl_xor_sync(0xffffffffu, lB, off);
            rA += __shfl_xor_sync(0xffffffffu, rA, off);
            rB += __shfl_xor_sync(0xffffffffu, rB, off);
        }
        if ((tc & 7) == 0 && gn < n_nodes) {
            g_sl[(size_t)gn * NHEAD + headA]     = lA;
            g_sl[(size_t)gn * NHEAD + headA + 2] = lB;
            g_sr[(size_t)gn * NHEAD + headA]     = rA;
            g_sr[(size_t)gn * NHEAD + headA + 2] = rB;
        }
    }
}

// ---------------- K5: warp-per-node aggregation (fp16 h gather) ----------
__device__ __forceinline__ float lrelu_exp(float a)
{
    float t = (a > 0.f) ? a : 0.2f * a;
    return __expf(t);
}

__global__ __launch_bounds__(256)
void aggregate_kernel(float* __restrict__ out, int n_nodes, int n_edges)
{
    int warp = (blockIdx.x * blockDim.x + threadIdx.x) >> 5;
    int lane = threadIdx.x & 31;
    if (warp >= n_nodes) return;

    int beg = g_rowptr[warp];
    int end = g_rowptr[warp + 1];
    beg = min(max(beg, 0), n_edges);
    end = min(max(end, beg), n_edges);
    int head = lane >> 3;

    float srh = g_sr[(size_t)warp * NHEAD + head];

    const uint2* __restrict__ h4 = (const uint2*)g_h2;   // 4 halfs per lane
    const int*   __restrict__ csr = g_csr_src;

    float4 acc = make_float4(0.f, 0.f, 0.f, 0.f);
    float den = 0.f;

    int j = beg;
    for (; j + 3 < end; j += 4) {
        int s0 = csr[j], s1 = csr[j + 1], s2 = csr[j + 2], s3 = csr[j + 3];
        float w0 = g_sl[(size_t)s0 * NHEAD + head];
        float w1 = g_sl[(size_t)s1 * NHEAD + head];
        float w2 = g_sl[(size_t)s2 * NHEAD + head];
        float w3 = g_sl[(size_t)s3 * NHEAD + head];
        uint2 u0 = h4[(size_t)s0 * 32 + lane];
        uint2 u1 = h4[(size_t)s1 * 32 + lane];
        uint2 u2 = h4[(size_t)s2 * 32 + lane];
        uint2 u3 = h4[(size_t)s3 * 32 + lane];
        float e0 = lrelu_exp(w0 + srh);
        float e1 = lrelu_exp(w1 + srh);
        float e2 = lrelu_exp(w2 + srh);
        float e3 = lrelu_exp(w3 + srh);
        float2 a0 = __half22float2(*(__half2*)&u0.x), b0 = __half22float2(*(__half2*)&u0.y);
        float2 a1 = __half22float2(*(__half2*)&u1.x), b1 = __half22float2(*(__half2*)&u1.y);
        float2 a2 = __half22float2(*(__half2*)&u2.x), b2 = __half22float2(*(__half2*)&u2.y);
        float2 a3 = __half22float2(*(__half2*)&u3.x), b3 = __half22float2(*(__half2*)&u3.y);
        acc.x += a0.x * e0 + a1.x * e1 + a2.x * e2 + a3.x * e3;
        acc.y += a0.y * e0 + a1.y * e1 + a2.y * e2 + a3.y * e3;
        acc.z += b0.x * e0 + b1.x * e1 + b2.x * e2 + b3.x * e3;
        acc.w += b0.y * e0 + b1.y * e1 + b2.y * e2 + b3.y * e3;
        den   += e0 + e1 + e2 + e3;
    }
    for (; j < end; ++j) {
        int s = csr[j];
        float ee = lrelu_exp(g_sl[(size_t)s * NHEAD + head] + srh);
        uint2 u = h4[(size_t)s * 32 + lane];
        float2 a = __half22float2(*(__half2*)&u.x);
        float2 b = __half22float2(*(__half2*)&u.y);
        acc.x += a.x * ee; acc.y += a.y * ee;
        acc.z += b.x * ee; acc.w += b.y * ee;
        den += ee;
    }

    float inv = 1.f / (den + 1e-8f);
    float4 o = make_float4(acc.x * inv, acc.y * inv, acc.z * inv, acc.w * inv);
    *(float4*)&out[(size_t)warp * OUTF + lane * 4] = o;
}

// ---------------- launch ---------------------------------------------------
extern "C" void kernel_launch(void* const* d_in, const int* in_sizes, int n_in,
                              void* d_out, int out_size)
{
    const float* x   = (const float*)d_in[0];
    const int*   ei  = (const int*)d_in[1];     // int32 OR int64 (detected)
    const float* W   = (const float*)d_in[2];
    const float* al  = (const float*)d_in[3];
    const float* ar  = (const float*)d_in[4];
    float* out = (float*)d_out;

    int n_nodes = in_sizes[0] / INF_DIM;
    int n_edges = in_sizes[1] / 2;
    if (n_nodes > MAXN) n_nodes = MAXN;
    if (n_edges > MAXE) n_edges = MAXE;

    // K1: normalize + degree histogram (g_deg zero by invariant)
    normalize_kernel<<<(n_edges + 255) / 256, 256>>>(ei, n_edges, n_nodes);

    // K2/K3: scan -> rowptr, cursor
    int scan_blocks = (n_nodes + 1023) / 1024;
    scan1_kernel<<<scan_blocks, 1024>>>(n_nodes);
    scan3_kernel<<<(n_nodes + 255) / 256, 256>>>(n_nodes, n_edges, scan_blocks);

    // K4: fat kernel — GEMM(+scalars, fp16 h) || scatter
    int gemm_blocks = (n_nodes + 127) / 128;
    int scat_blocks = (n_edges + 255) / 256;
    fat_kernel<<<gemm_blocks + scat_blocks, 256>>>(x, W, al, ar,
                                                   n_nodes, n_edges, gemm_blocks);

    // K5: aggregate (fp16 h gather)
    int warps_blocks = (n_nodes * 32 + 255) / 256;
    aggregate_kernel<<<warps_blocks, 256>>>(out, n_nodes, n_edges);
}

// round 8
// speedup vs baseline: 1.4560x; 1.1407x over previous
#include <cuda_runtime.h>
#include <cuda_fp16.h>
#include <mma.h>

using namespace nvcuda;

// ---------------- problem constants (fixed-shape problem) ----------------
#define MAXN 100000
#define MAXE 1600000
#define INF_DIM 128
#define OUTF 128          // H*D
#define NHEAD 4

// dynamic smem: xs[128][136] half + ws[128][136] half, reused as csm[128][132] f32
#define XS_LD 136
#define CS_LD 132
#define SMEM_FAT (2 * 128 * XS_LD * 2)   // 69632 bytes

// ---------------- device scratch (no allocations allowed) ----------------
// g_deg zero-state invariant: zero-initialized at load; scan1 re-zeros each
// entry after consuming it, so every launch (incl. graph replays) sees 0.
__device__ __align__(16) __half2 g_h2[(size_t)MAXN * 64];   // 25.6 MB (fp16 h)
__device__ __align__(16) float   g_sl[(size_t)MAXN * NHEAD];
__device__ __align__(16) float   g_sr[(size_t)MAXN * NHEAD];
__device__ int    g_deg[MAXN];
__device__ int    g_rowptr[MAXN + 1];
__device__ int    g_cursor[MAXN];
__device__ int    g_bsum[128];
__device__ int    g_src[MAXE];                    // 6.4 MB
__device__ int    g_dst[MAXE];                    // 6.4 MB
__device__ int    g_csr_src[MAXE];                // 6.4 MB

// ---------------- K1: normalize edge_index + degree histogram ------------
__global__ void normalize_kernel(const int* __restrict__ raw,
                                 int n_edges, int n_nodes)
{
    __shared__ int is64_sh;
    if (threadIdx.x == 0) {
        int acc = 0;
        for (int i = 0; i < 64; ++i) acc |= raw[2 * i + 1];
        is64_sh = (acc == 0) ? 1 : 0;
    }
    __syncthreads();
    int is64 = is64_sh;
    int e = blockIdx.x * blockDim.x + threadIdx.x;
    if (e >= n_edges) return;
    int s, d;
    if (is64) {
        s = raw[(size_t)e * 2];
        d = raw[((size_t)n_edges + e) * 2];
    } else {
        s = raw[e];
        d = raw[n_edges + e];
    }
    s = min(max(s, 0), n_nodes - 1);
    d = min(max(d, 0), n_nodes - 1);
    g_src[e] = s;
    g_dst[e] = d;
    atomicAdd(&g_deg[d], 1);
}

// ---------------- K2: scan part 1 (per-1024-chunk) + deg re-zero ----------
__global__ __launch_bounds__(1024)
void scan1_kernel(int n_nodes)
{
    __shared__ int sh[1024];
    int i = blockIdx.x * 1024 + threadIdx.x;
    int v = 0;
    if (i < n_nodes) {
        v = g_deg[i];
        g_deg[i] = 0;
    }
    sh[threadIdx.x] = v;
    __syncthreads();
    int xval = v;
#pragma unroll
    for (int off = 1; off < 1024; off <<= 1) {
        int t = (threadIdx.x >= off) ? sh[threadIdx.x - off] : 0;
        __syncthreads();
        xval += t;
        sh[threadIdx.x] = xval;
        __syncthreads();
    }
    if (i < n_nodes) g_rowptr[i] = xval - v;
    if (threadIdx.x == 1023) g_bsum[blockIdx.x] = xval;
}

// ---------------- K3: scan part 2 (embedded bsum scan) + cursor init ------
__global__ __launch_bounds__(256)
void scan3_kernel(int n_nodes, int n_edges, int nblocks)  // nblocks <= 128
{
    __shared__ int sb[128];
    int t = threadIdx.x;
    if (t < 128) sb[t] = (t < nblocks) ? g_bsum[t] : 0;
    __syncthreads();
    if (t < 128) {
        int v = sb[t];
        int xval = v;
#pragma unroll
        for (int off = 1; off < 128; off <<= 1) {
            int tv = (t >= off) ? sb[t - off] : 0;
            __syncthreads();
            xval += tv;
            sb[t] = xval;
            __syncthreads();
        }
        sb[t] = xval - v;
    } else {
#pragma unroll
        for (int off = 1; off < 128; off <<= 1) { __syncthreads(); __syncthreads(); }
    }
    __syncthreads();

    int i = blockIdx.x * blockDim.x + t;
    if (i < n_nodes) {
        int r = g_rowptr[i] + sb[i >> 10];
        g_rowptr[i] = r;
        g_cursor[i] = r;
    }
    if (i == 0) g_rowptr[n_nodes] = n_edges;
}

// ---------------- K4 (fat): tensor-core GEMM+scalars  ||  scatter ---------
// Blocks [0, gemm_blocks): h = x@W^T via fp16 HMMA (fp32 accum), fused
// attention scalars from the f32 accumulator. Blocks above: CSR scatter.
__global__ __launch_bounds__(256)
void fat_kernel(const float* __restrict__ x, const float* __restrict__ W,
                const float* __restrict__ al, const float* __restrict__ ar,
                int n_nodes, int n_edges, int gemm_blocks)
{
    extern __shared__ char smem_raw[];
    const int tid = threadIdx.x;

    if (blockIdx.x >= gemm_blocks) {
        // ---------------- scatter part (no smem use) ----------------
        int e = (blockIdx.x - gemm_blocks) * 256 + tid;
        if (e >= n_edges) return;
        int s = g_src[e];
        int d = g_dst[e];
        int pos = atomicAdd(&g_cursor[d], 1);
        pos = min(max(pos, 0), MAXE - 1);
        g_csr_src[pos] = s;
        return;
    }

    // ---------------- GEMM part ----------------
    __half* xs = (__half*)smem_raw;              // [128][XS_LD]
    __half* ws = xs + 128 * XS_LD;               // [128][XS_LD]
    float*  csm = (float*)smem_raw;              // reused: [128][CS_LD]

    const int n0 = blockIdx.x * 128;

    // load + convert x tile and W to fp16 smem (4096 float4s, 16 per thread)
#pragma unroll
    for (int i = 0; i < 16; ++i) {
        int idx = i * 256 + tid;          // float4 index 0..4095
        int row = idx >> 5;
        int c4  = idx & 31;
        int gn  = n0 + row;
        float4 v = make_float4(0.f, 0.f, 0.f, 0.f);
        if (gn < n_nodes) v = ((const float4*)x)[(size_t)gn * 32 + c4];
        *(__half2*)&xs[row * XS_LD + c4 * 4]     = __floats2half2_rn(v.x, v.y);
        *(__half2*)&xs[row * XS_LD + c4 * 4 + 2] = __floats2half2_rn(v.z, v.w);
        float4 wv = ((const float4*)W)[idx];
        *(__half2*)&ws[row * XS_LD + c4 * 4]     = __floats2half2_rn(wv.x, wv.y);
        *(__half2*)&ws[row * XS_LD + c4 * 4 + 2] = __floats2half2_rn(wv.z, wv.w);
    }
    __syncthreads();

    // warp layout: 4 row-groups x 2 col-groups; each warp 32x64 output
    const int w    = tid >> 5;
    const int lane = tid & 31;
    const int wr   = (w & 3) * 32;
    const int wc   = (w >> 2) * 64;

    wmma::fragment<wmma::accumulator, 16, 16, 16, float> c[2][4];
#pragma unroll
    for (int i = 0; i < 2; ++i)
#pragma unroll
        for (int j = 0; j < 4; ++j) wmma::fill_fragment(c[i][j], 0.f);

#pragma unroll
    for (int kk = 0; kk < 8; ++kk) {
        int k = kk * 16;
        wmma::fragment<wmma::matrix_a, 16, 16, 16, __half, wmma::row_major> a[2];
        wmma::fragment<wmma::matrix_b, 16, 16, 16, __half, wmma::col_major> b[4];
        wmma::load_matrix_sync(a[0], &xs[(wr +  0) * XS_LD + k], XS_LD);
        wmma::load_matrix_sync(a[1], &xs[(wr + 16) * XS_LD + k], XS_LD);
#pragma unroll
        for (int j = 0; j < 4; ++j)
            wmma::load_matrix_sync(b[j], &ws[(wc + j * 16) * XS_LD + k], XS_LD);
#pragma unroll
        for (int i = 0; i < 2; ++i)
#pragma unroll
            for (int j = 0; j < 4; ++j)
                wmma::mma_sync(c[i][j], a[i], b[j], c[i][j]);
    }
    __syncthreads();   // done reading xs/ws; reuse smem as csm

#pragma unroll
    for (int i = 0; i < 2; ++i)
#pragma unroll
        for (int j = 0; j < 4; ++j)
            wmma::store_matrix_sync(&csm[(wr + i * 16) * CS_LD + wc + j * 16],
                                    c[i][j], CS_LD, wmma::mem_row_major);
    __syncthreads();

    // epilogue: per-row scalars (f32) + fp16 h store
    float4 alv = ((const float4*)al)[lane];   // [H,D] flat: cols lane*4..+3
    float4 arv = ((const float4*)ar)[lane];
    const int head = lane >> 3;

    for (int r = w; r < 128; r += 8) {
        int gn = n0 + r;
        float4 hv = *(float4*)&csm[r * CS_LD + lane * 4];

        if (gn < n_nodes) {
            g_h2[(size_t)gn * 64 + lane * 2]     = __floats2half2_rn(hv.x, hv.y);
            g_h2[(size_t)gn * 64 + lane * 2 + 1] = __floats2half2_rn(hv.z, hv.w);
        }

        float sl = hv.x * alv.x + hv.y * alv.y + hv.z * alv.z + hv.w * alv.w;
        float sr = hv.x * arv.x + hv.y * arv.y + hv.z * arv.z + hv.w * arv.w;
#pragma unroll
        for (int off = 1; off <= 4; off <<= 1) {
            sl += __shfl_xor_sync(0xffffffffu, sl, off);
            sr += __shfl_xor_sync(0xffffffffu, sr, off);
        }
        if ((lane & 7) == 0 && gn < n_nodes) {
            g_sl[(size_t)gn * NHEAD + head] = sl;
            g_sr[(size_t)gn * NHEAD + head] = sr;
        }
    }
}

// ---------------- K5: warp-per-node aggregation (fp16 h gather) ----------
__device__ __forceinline__ float lrelu_exp(float a)
{
    float t = (a > 0.f) ? a : 0.2f * a;
    return __expf(t);
}

__global__ __launch_bounds__(256)
void aggregate_kernel(float* __restrict__ out, int n_nodes, int n_edges)
{
    int warp = (blockIdx.x * blockDim.x + threadIdx.x) >> 5;
    int lane = threadIdx.x & 31;
    if (warp >= n_nodes) return;

    int beg = g_rowptr[warp];
    int end = g_rowptr[warp + 1];
    beg = min(max(beg, 0), n_edges);
    end = min(max(end, beg), n_edges);
    int head = lane >> 3;

    float srh = g_sr[(size_t)warp * NHEAD + head];

    const uint2* __restrict__ h4 = (const uint2*)g_h2;   // 4 halfs per lane
    const int*   __restrict__ csr = g_csr_src;

    float4 acc = make_float4(0.f, 0.f, 0.f, 0.f);
    float den = 0.f;

    int j = beg;
    for (; j + 3 < end; j += 4) {
        int s0 = csr[j], s1 = csr[j + 1], s2 = csr[j + 2], s3 = csr[j + 3];
        float w0 = g_sl[(size_t)s0 * NHEAD + head];
        float w1 = g_sl[(size_t)s1 * NHEAD + head];
        float w2 = g_sl[(size_t)s2 * NHEAD + head];
        float w3 = g_sl[(size_t)s3 * NHEAD + head];
        uint2 u0 = h4[(size_t)s0 * 32 + lane];
        uint2 u1 = h4[(size_t)s1 * 32 + lane];
        uint2 u2 = h4[(size_t)s2 * 32 + lane];
        uint2 u3 = h4[(size_t)s3 * 32 + lane];
        float e0 = lrelu_exp(w0 + srh);
        float e1 = lrelu_exp(w1 + srh);
        float e2 = lrelu_exp(w2 + srh);
        float e3 = lrelu_exp(w3 + srh);
        float2 a0 = __half22float2(*(__half2*)&u0.x), b0 = __half22float2(*(__half2*)&u0.y);
        float2 a1 = __half22float2(*(__half2*)&u1.x), b1 = __half22float2(*(__half2*)&u1.y);
        float2 a2 = __half22float2(*(__half2*)&u2.x), b2 = __half22float2(*(__half2*)&u2.y);
        float2 a3 = __half22float2(*(__half2*)&u3.x), b3 = __half22float2(*(__half2*)&u3.y);
        acc.x += a0.x * e0 + a1.x * e1 + a2.x * e2 + a3.x * e3;
        acc.y += a0.y * e0 + a1.y * e1 + a2.y * e2 + a3.y * e3;
        acc.z += b0.x * e0 + b1.x * e1 + b2.x * e2 + b3.x * e3;
        acc.w += b0.y * e0 + b1.y * e1 + b2.y * e2 + b3.y * e3;
        den   += e0 + e1 + e2 + e3;
    }
    for (; j < end; ++j) {
        int s = csr[j];
        float ee = lrelu_exp(g_sl[(size_t)s * NHEAD + head] + srh);
        uint2 u = h4[(size_t)s * 32 + lane];
        float2 a = __half22float2(*(__half2*)&u.x);
        float2 b = __half22float2(*(__half2*)&u.y);
        acc.x += a.x * ee; acc.y += a.y * ee;
        acc.z += b.x * ee; acc.w += b.y * ee;
        den += ee;
    }

    float inv = 1.f / (den + 1e-8f);
    float4 o = make_float4(acc.x * inv, acc.y * inv, acc.z * inv, acc.w * inv);
    *(float4*)&out[(size_t)warp * OUTF + lane * 4] = o;
}

// ---------------- launch ---------------------------------------------------
extern "C" void kernel_launch(void* const* d_in, const int* in_sizes, int n_in,
                              void* d_out, int out_size)
{
    const float* x   = (const float*)d_in[0];
    const int*   ei  = (const int*)d_in[1];     // int32 OR int64 (detected)
    const float* W   = (const float*)d_in[2];
    const float* al  = (const float*)d_in[3];
    const float* ar  = (const float*)d_in[4];
    float* out = (float*)d_out;

    int n_nodes = in_sizes[0] / INF_DIM;
    int n_edges = in_sizes[1] / 2;
    if (n_nodes > MAXN) n_nodes = MAXN;
    if (n_edges > MAXE) n_edges = MAXE;

    // allow 70KB dynamic smem for the fat kernel (idempotent host call)
    static bool attr_set = false;
    if (!attr_set) {
        cudaFuncSetAttribute(fat_kernel,
                             cudaFuncAttributeMaxDynamicSharedMemorySize,
                             SMEM_FAT);
        attr_set = true;
    }

    // K1: normalize + degree histogram (g_deg zero by invariant)
    normalize_kernel<<<(n_edges + 255) / 256, 256>>>(ei, n_edges, n_nodes);

    // K2/K3: scan -> rowptr, cursor
    int scan_blocks = (n_nodes + 1023) / 1024;
    scan1_kernel<<<scan_blocks, 1024>>>(n_nodes);
    scan3_kernel<<<(n_nodes + 255) / 256, 256>>>(n_nodes, n_edges, scan_blocks);

    // K4: fat kernel — tensor-core GEMM(+scalars, fp16 h) || scatter
    int gemm_blocks = (n_nodes + 127) / 128;
    int scat_blocks = (n_edges + 255) / 256;
    fat_kernel<<<gemm_blocks + scat_blocks, 256, SMEM_FAT>>>(
        x, W, al, ar, n_nodes, n_edges, gemm_blocks);

    // K5: aggregate (fp16 h gather)
    int warps_blocks = (n_nodes * 32 + 255) / 256;
    aggregate_kernel<<<warps_blocks, 256>>>(out, n_nodes, n_edges);
}

// round 9
// speedup vs baseline: 1.7513x; 1.2028x over previous
#include <cuda_runtime.h>
#include <cuda_fp16.h>
#include <mma.h>

using namespace nvcuda;

// ---------------- problem constants (fixed-shape problem) ----------------
#define MAXN 100000
#define MAXE 1600000
#define INF_DIM 128
#define OUTF 128          // H*D
#define NHEAD 4

// dynamic smem: xs[128][136] half + ws[128][136] half, reused as csm[128][132] f32
#define XS_LD 136
#define CS_LD 132
#define SMEM_GEMM (2 * 128 * XS_LD * 2)   // 69632 bytes

// ---------------- device scratch (no allocations allowed) ----------------
// g_deg zero-state invariant: zero-initialized at load; scan1 re-zeros each
// entry after consuming it, so every launch (incl. graph replays) sees 0.
__device__ __align__(16) __half2 g_h2[(size_t)MAXN * 64];   // 25.6 MB (fp16 h)
__device__ __align__(16) float   g_sl[(size_t)MAXN * NHEAD];
__device__ __align__(16) float   g_sr[(size_t)MAXN * NHEAD];
__device__ int    g_deg[MAXN];
__device__ int    g_rowptr[MAXN + 1];
__device__ int    g_cursor[MAXN];
__device__ int    g_bsum[128];
__device__ int    g_src[MAXE];                    // 6.4 MB
__device__ int    g_dst[MAXE];                    // 6.4 MB
__device__ int    g_csr_src[MAXE];                // 6.4 MB

// ---------------- K1: normalize edge_index + degree histogram ------------
__global__ void normalize_kernel(const int* __restrict__ raw,
                                 int n_edges, int n_nodes)
{
    __shared__ int is64_sh;
    if (threadIdx.x == 0) {
        int acc = 0;
        for (int i = 0; i < 64; ++i) acc |= raw[2 * i + 1];
        is64_sh = (acc == 0) ? 1 : 0;
    }
    __syncthreads();
    int is64 = is64_sh;
    int e = blockIdx.x * blockDim.x + threadIdx.x;
    if (e >= n_edges) return;
    int s, d;
    if (is64) {
        s = raw[(size_t)e * 2];
        d = raw[((size_t)n_edges + e) * 2];
    } else {
        s = raw[e];
        d = raw[n_edges + e];
    }
    s = min(max(s, 0), n_nodes - 1);
    d = min(max(d, 0), n_nodes - 1);
    g_src[e] = s;
    g_dst[e] = d;
    atomicAdd(&g_deg[d], 1);
}

// ---------------- K2: scan part 1 (per-1024-chunk) + deg re-zero ----------
__global__ __launch_bounds__(1024)
void scan1_kernel(int n_nodes)
{
    __shared__ int sh[1024];
    int i = blockIdx.x * 1024 + threadIdx.x;
    int v = 0;
    if (i < n_nodes) {
        v = g_deg[i];
        g_deg[i] = 0;
    }
    sh[threadIdx.x] = v;
    __syncthreads();
    int xval = v;
#pragma unroll
    for (int off = 1; off < 1024; off <<= 1) {
        int t = (threadIdx.x >= off) ? sh[threadIdx.x - off] : 0;
        __syncthreads();
        xval += t;
        sh[threadIdx.x] = xval;
        __syncthreads();
    }
    if (i < n_nodes) g_rowptr[i] = xval - v;
    if (threadIdx.x == 1023) g_bsum[blockIdx.x] = xval;
}

// ---------------- K3: scan part 2 (embedded bsum scan) + cursor init ------
__global__ __launch_bounds__(256)
void scan3_kernel(int n_nodes, int n_edges, int nblocks)  // nblocks <= 128
{
    __shared__ int sb[128];
    int t = threadIdx.x;
    if (t < 128) sb[t] = (t < nblocks) ? g_bsum[t] : 0;
    __syncthreads();
    if (t < 128) {
        int v = sb[t];
        int xval = v;
#pragma unroll
        for (int off = 1; off < 128; off <<= 1) {
            int tv = (t >= off) ? sb[t - off] : 0;
            __syncthreads();
            xval += tv;
            sb[t] = xval;
            __syncthreads();
        }
        sb[t] = xval - v;
    } else {
#pragma unroll
        for (int off = 1; off < 128; off <<= 1) { __syncthreads(); __syncthreads(); }
    }
    __syncthreads();

    int i = blockIdx.x * blockDim.x + t;
    if (i < n_nodes) {
        int r = g_rowptr[i] + sb[i >> 10];
        g_rowptr[i] = r;
        g_cursor[i] = r;
    }
    if (i == 0) g_rowptr[n_nodes] = n_edges;
}

// ---------------- K4: scatter (lean: 0 smem, low regs, full occ) ----------
__global__ __launch_bounds__(256)
void scatter_kernel(int n_edges)
{
    int e = blockIdx.x * blockDim.x + threadIdx.x;
    if (e >= n_edges) return;
    int s = g_src[e];
    int d = g_dst[e];
    int pos = atomicAdd(&g_cursor[d], 1);
    pos = min(max(pos, 0), MAXE - 1);
    g_csr_src[pos] = s;
}

// ---------------- K5: tensor-core GEMM + fused scalars (side stream) ------
__global__ __launch_bounds__(256)
void gemm_kernel(const float* __restrict__ x, const float* __restrict__ W,
                 const float* __restrict__ al, const float* __restrict__ ar,
                 int n_nodes)
{
    extern __shared__ char smem_raw[];
    const int tid = threadIdx.x;

    __half* xs = (__half*)smem_raw;              // [128][XS_LD]
    __half* ws = xs + 128 * XS_LD;               // [128][XS_LD]
    float*  csm = (float*)smem_raw;              // reused: [128][CS_LD]

    const int n0 = blockIdx.x * 128;

    // load + convert x tile and W to fp16 smem (4096 float4s, 16 per thread)
#pragma unroll
    for (int i = 0; i < 16; ++i) {
        int idx = i * 256 + tid;          // float4 index 0..4095
        int row = idx >> 5;
        int c4  = idx & 31;
        int gn  = n0 + row;
        float4 v = make_float4(0.f, 0.f, 0.f, 0.f);
        if (gn < n_nodes) v = ((const float4*)x)[(size_t)gn * 32 + c4];
        *(__half2*)&xs[row * XS_LD + c4 * 4]     = __floats2half2_rn(v.x, v.y);
        *(__half2*)&xs[row * XS_LD + c4 * 4 + 2] = __floats2half2_rn(v.z, v.w);
        float4 wv = ((const float4*)W)[idx];
        *(__half2*)&ws[row * XS_LD + c4 * 4]     = __floats2half2_rn(wv.x, wv.y);
        *(__half2*)&ws[row * XS_LD + c4 * 4 + 2] = __floats2half2_rn(wv.z, wv.w);
    }
    __syncthreads();

    // warp layout: 4 row-groups x 2 col-groups; each warp 32x64 output
    const int w    = tid >> 5;
    const int lane = tid & 31;
    const int wr   = (w & 3) * 32;
    const int wc   = (w >> 2) * 64;

    wmma::fragment<wmma::accumulator, 16, 16, 16, float> c[2][4];
#pragma unroll
    for (int i = 0; i < 2; ++i)
#pragma unroll
        for (int j = 0; j < 4; ++j) wmma::fill_fragment(c[i][j], 0.f);

#pragma unroll
    for (int kk = 0; kk < 8; ++kk) {
        int k = kk * 16;
        wmma::fragment<wmma::matrix_a, 16, 16, 16, __half, wmma::row_major> a[2];
        wmma::fragment<wmma::matrix_b, 16, 16, 16, __half, wmma::col_major> b[4];
        wmma::load_matrix_sync(a[0], &xs[(wr +  0) * XS_LD + k], XS_LD);
        wmma::load_matrix_sync(a[1], &xs[(wr + 16) * XS_LD + k], XS_LD);
#pragma unroll
        for (int j = 0; j < 4; ++j)
            wmma::load_matrix_sync(b[j], &ws[(wc + j * 16) * XS_LD + k], XS_LD);
#pragma unroll
        for (int i = 0; i < 2; ++i)
#pragma unroll
            for (int j = 0; j < 4; ++j)
                wmma::mma_sync(c[i][j], a[i], b[j], c[i][j]);
    }
    __syncthreads();   // done reading xs/ws; reuse smem as csm

#pragma unroll
    for (int i = 0; i < 2; ++i)
#pragma unroll
        for (int j = 0; j < 4; ++j)
            wmma::store_matrix_sync(&csm[(wr + i * 16) * CS_LD + wc + j * 16],
                                    c[i][j], CS_LD, wmma::mem_row_major);
    __syncthreads();

    // epilogue: per-row scalars (f32) + fp16 h store
    float4 alv = ((const float4*)al)[lane];   // [H,D] flat: cols lane*4..+3
    float4 arv = ((const float4*)ar)[lane];
    const int head = lane >> 3;

    for (int r = w; r < 128; r += 8) {
        int gn = n0 + r;
        float4 hv = *(float4*)&csm[r * CS_LD + lane * 4];

        if (gn < n_nodes) {
            g_h2[(size_t)gn * 64 + lane * 2]     = __floats2half2_rn(hv.x, hv.y);
            g_h2[(size_t)gn * 64 + lane * 2 + 1] = __floats2half2_rn(hv.z, hv.w);
        }

        float sl = hv.x * alv.x + hv.y * alv.y + hv.z * alv.z + hv.w * alv.w;
        float sr = hv.x * arv.x + hv.y * arv.y + hv.z * arv.z + hv.w * arv.w;
#pragma unroll
        for (int off = 1; off <= 4; off <<= 1) {
            sl += __shfl_xor_sync(0xffffffffu, sl, off);
            sr += __shfl_xor_sync(0xffffffffu, sr, off);
        }
        if ((lane & 7) == 0 && gn < n_nodes) {
            g_sl[(size_t)gn * NHEAD + head] = sl;
            g_sr[(size_t)gn * NHEAD + head] = sr;
        }
    }
}

// ---------------- K6: warp-per-node aggregation (fp16 h, MLP x8) ---------
__device__ __forceinline__ float lrelu_exp(float a)
{
    float t = (a > 0.f) ? a : 0.2f * a;
    return __expf(t);
}

__global__ __launch_bounds__(256)
void aggregate_kernel(float* __restrict__ out, int n_nodes, int n_edges)
{
    int warp = (blockIdx.x * blockDim.x + threadIdx.x) >> 5;
    int lane = threadIdx.x & 31;
    if (warp >= n_nodes) return;

    int beg = g_rowptr[warp];
    int end = g_rowptr[warp + 1];
    beg = min(max(beg, 0), n_edges);
    end = min(max(end, beg), n_edges);
    int head = lane >> 3;

    float srh = g_sr[(size_t)warp * NHEAD + head];

    const uint2* __restrict__ h4 = (const uint2*)g_h2;   // 4 halfs per lane
    const int*   __restrict__ csr = g_csr_src;

    float4 acc = make_float4(0.f, 0.f, 0.f, 0.f);
    float den = 0.f;

    int j = beg;
    // MLP x8: 8 independent gather chains in flight
    for (; j + 7 < end; j += 8) {
        int   sx[8];
        float wx[8];
        uint2 ux[8];
#pragma unroll
        for (int q = 0; q < 8; ++q) sx[q] = csr[j + q];
#pragma unroll
        for (int q = 0; q < 8; ++q) wx[q] = g_sl[(size_t)sx[q] * NHEAD + head];
#pragma unroll
        for (int q = 0; q < 8; ++q) ux[q] = h4[(size_t)sx[q] * 32 + lane];
#pragma unroll
        for (int q = 0; q < 8; ++q) {
            float ee = lrelu_exp(wx[q] + srh);
            float2 a = __half22float2(*(__half2*)&ux[q].x);
            float2 b = __half22float2(*(__half2*)&ux[q].y);
            acc.x += a.x * ee; acc.y += a.y * ee;
            acc.z += b.x * ee; acc.w += b.y * ee;
            den += ee;
        }
    }
    for (; j < end; ++j) {
        int s = csr[j];
        float ee = lrelu_exp(g_sl[(size_t)s * NHEAD + head] + srh);
        uint2 u = h4[(size_t)s * 32 + lane];
        float2 a = __half22float2(*(__half2*)&u.x);
        float2 b = __half22float2(*(__half2*)&u.y);
        acc.x += a.x * ee; acc.y += a.y * ee;
        acc.z += b.x * ee; acc.w += b.y * ee;
        den += ee;
    }

    float inv = 1.f / (den + 1e-8f);
    float4 o = make_float4(acc.x * inv, acc.y * inv, acc.z * inv, acc.w * inv);
    *(float4*)&out[(size_t)warp * OUTF + lane * 4] = o;
}

// ---------------- launch ---------------------------------------------------
extern "C" void kernel_launch(void* const* d_in, const int* in_sizes, int n_in,
                              void* d_out, int out_size)
{
    const float* x   = (const float*)d_in[0];
    const int*   ei  = (const int*)d_in[1];     // int32 OR int64 (detected)
    const float* W   = (const float*)d_in[2];
    const float* al  = (const float*)d_in[3];
    const float* ar  = (const float*)d_in[4];
    float* out = (float*)d_out;

    int n_nodes = in_sizes[0] / INF_DIM;
    int n_edges = in_sizes[1] / 2;
    if (n_nodes > MAXN) n_nodes = MAXN;
    if (n_edges > MAXE) n_edges = MAXE;

    // one-time host resources (created on the uncaptured correctness call)
    static bool init = false;
    static cudaStream_t s2;
    static cudaEvent_t ev_fork, ev_join;
    if (!init) {
        cudaFuncSetAttribute(gemm_kernel,
                             cudaFuncAttributeMaxDynamicSharedMemorySize,
                             SMEM_GEMM);
        cudaStreamCreateWithFlags(&s2, cudaStreamNonBlocking);
        cudaEventCreateWithFlags(&ev_fork, cudaEventDisableTiming);
        cudaEventCreateWithFlags(&ev_join, cudaEventDisableTiming);
        init = true;
    }

    // fork: GEMM(+scalars) on side stream, edge chain on main stream
    cudaEventRecord(ev_fork, 0);
    cudaStreamWaitEvent(s2, ev_fork, 0);

    int gemm_blocks = (n_nodes + 127) / 128;
    gemm_kernel<<<gemm_blocks, 256, SMEM_GEMM, s2>>>(x, W, al, ar, n_nodes);
    cudaEventRecord(ev_join, s2);

    // edge chain (main stream): normalize -> scan -> scatter
    normalize_kernel<<<(n_edges + 255) / 256, 256>>>(ei, n_edges, n_nodes);
    int scan_blocks = (n_nodes + 1023) / 1024;
    scan1_kernel<<<scan_blocks, 1024>>>(n_nodes);
    scan3_kernel<<<(n_nodes + 255) / 256, 256>>>(n_nodes, n_edges, scan_blocks);
    scatter_kernel<<<(n_edges + 255) / 256, 256>>>(n_edges);

    // join: aggregate needs both CSR (main) and h/sl/sr (side)
    cudaStreamWaitEvent(0, ev_join, 0);
    int warps_blocks = (n_nodes * 32 + 255) / 256;
    aggregate_kernel<<<warps_blocks, 256>>>(out, n_nodes, n_edges);
}

// round 10
// speedup vs baseline: 1.7781x; 1.0153x over previous
#include <cuda_runtime.h>
#include <cuda_fp16.h>
#include <mma.h>

using namespace nvcuda;

// ---------------- problem constants (fixed-shape problem) ----------------
#define MAXN 100000
#define MAXE 1600000
#define INF_DIM 128
#define OUTF 128          // H*D
#define NHEAD 4

// dynamic smem: xs[128][136] half + ws[128][136] half, reused as csm[128][132] f32
#define XS_LD 136
#define CS_LD 132
#define SMEM_GEMM (2 * 128 * XS_LD * 2)   // 69632 bytes

// ---------------- device scratch (no allocations allowed) ----------------
// g_deg zero-state invariant: zero-initialized at load; scan1 re-zeros each
// entry after consuming it, so every launch (incl. graph replays) sees 0.
__device__ __align__(16) __half2 g_h2[(size_t)MAXN * 64];   // 25.6 MB (fp16 h)
__device__ __align__(16) float   g_sl[(size_t)MAXN * NHEAD];
__device__ __align__(16) float   g_sr[(size_t)MAXN * NHEAD];
__device__ int    g_deg[MAXN];
__device__ int    g_rowptr[MAXN + 1];
__device__ int    g_bsum[128];
__device__ int    g_src[MAXE];                    // 6.4 MB
__device__ int    g_dst[MAXE];                    // 6.4 MB
__device__ int    g_rank[MAXE];                   // 6.4 MB (rank within dst)
__device__ int    g_csr_src[MAXE];                // 6.4 MB

// ---------------- K1: normalize edge_index + degree hist + rank ----------
__global__ void normalize_kernel(const int* __restrict__ raw,
                                 int n_edges, int n_nodes)
{
    __shared__ int is64_sh;
    if (threadIdx.x == 0) {
        int acc = 0;
        for (int i = 0; i < 64; ++i) acc |= raw[2 * i + 1];
        is64_sh = (acc == 0) ? 1 : 0;
    }
    __syncthreads();
    int is64 = is64_sh;
    int e = blockIdx.x * blockDim.x + threadIdx.x;
    if (e >= n_edges) return;
    int s, d;
    if (is64) {
        s = raw[(size_t)e * 2];
        d = raw[((size_t)n_edges + e) * 2];
    } else {
        s = raw[e];
        d = raw[n_edges + e];
    }
    s = min(max(s, 0), n_nodes - 1);
    d = min(max(d, 0), n_nodes - 1);
    g_src[e] = s;
    g_dst[e] = d;
    g_rank[e] = atomicAdd(&g_deg[d], 1);   // rank of this edge within dst
}

// ---------------- K2: scan part 1 (per-1024-chunk) + deg re-zero ----------
__global__ __launch_bounds__(1024)
void scan1_kernel(int n_nodes)
{
    __shared__ int sh[1024];
    int i = blockIdx.x * 1024 + threadIdx.x;
    int v = 0;
    if (i < n_nodes) {
        v = g_deg[i];
        g_deg[i] = 0;
    }
    sh[threadIdx.x] = v;
    __syncthreads();
    int xval = v;
#pragma unroll
    for (int off = 1; off < 1024; off <<= 1) {
        int t = (threadIdx.x >= off) ? sh[threadIdx.x - off] : 0;
        __syncthreads();
        xval += t;
        sh[threadIdx.x] = xval;
        __syncthreads();
    }
    if (i < n_nodes) g_rowptr[i] = xval - v;
    if (threadIdx.x == 1023) g_bsum[blockIdx.x] = xval;
}

// ---------------- K3: scan part 2 (embedded bsum scan) --------------------
__global__ __launch_bounds__(256)
void scan3_kernel(int n_nodes, int n_edges, int nblocks)  // nblocks <= 128
{
    __shared__ int sb[128];
    int t = threadIdx.x;
    if (t < 128) sb[t] = (t < nblocks) ? g_bsum[t] : 0;
    __syncthreads();
    if (t < 128) {
        int v = sb[t];
        int xval = v;
#pragma unroll
        for (int off = 1; off < 128; off <<= 1) {
            int tv = (t >= off) ? sb[t - off] : 0;
            __syncthreads();
            xval += tv;
            sb[t] = xval;
            __syncthreads();
        }
        sb[t] = xval - v;
    } else {
#pragma unroll
        for (int off = 1; off < 128; off <<= 1) { __syncthreads(); __syncthreads(); }
    }
    __syncthreads();

    int i = blockIdx.x * blockDim.x + t;
    if (i < n_nodes)
        g_rowptr[i] += sb[i >> 10];
    if (i == 0) g_rowptr[n_nodes] = n_edges;
}

// ---------------- K4: scatter (atomic-free: pos = rowptr[d] + rank) ------
__global__ __launch_bounds__(256)
void scatter_kernel(int n_edges)
{
    int e = blockIdx.x * blockDim.x + threadIdx.x;
    if (e >= n_edges) return;
    int s = g_src[e];
    int d = g_dst[e];
    int pos = g_rowptr[d] + g_rank[e];
    pos = min(max(pos, 0), MAXE - 1);   // defensive
    g_csr_src[pos] = s;
}

// ---------------- K5: tensor-core GEMM + fused scalars (side stream) ------
__global__ __launch_bounds__(256)
void gemm_kernel(const float* __restrict__ x, const float* __restrict__ W,
                 const float* __restrict__ al, const float* __restrict__ ar,
                 int n_nodes)
{
    extern __shared__ char smem_raw[];
    const int tid = threadIdx.x;

    __half* xs = (__half*)smem_raw;              // [128][XS_LD]
    __half* ws = xs + 128 * XS_LD;               // [128][XS_LD]
    float*  csm = (float*)smem_raw;              // reused: [128][CS_LD]

    const int n0 = blockIdx.x * 128;

#pragma unroll
    for (int i = 0; i < 16; ++i) {
        int idx = i * 256 + tid;          // float4 index 0..4095
        int row = idx >> 5;
        int c4  = idx & 31;
        int gn  = n0 + row;
        float4 v = make_float4(0.f, 0.f, 0.f, 0.f);
        if (gn < n_nodes) v = ((const float4*)x)[(size_t)gn * 32 + c4];
        *(__half2*)&xs[row * XS_LD + c4 * 4]     = __floats2half2_rn(v.x, v.y);
        *(__half2*)&xs[row * XS_LD + c4 * 4 + 2] = __floats2half2_rn(v.z, v.w);
        float4 wv = ((const float4*)W)[idx];
        *(__half2*)&ws[row * XS_LD + c4 * 4]     = __floats2half2_rn(wv.x, wv.y);
        *(__half2*)&ws[row * XS_LD + c4 * 4 + 2] = __floats2half2_rn(wv.z, wv.w);
    }
    __syncthreads();

    const int w    = tid >> 5;
    const int lane = tid & 31;
    const int wr   = (w & 3) * 32;
    const int wc   = (w >> 2) * 64;

    wmma::fragment<wmma::accumulator, 16, 16, 16, float> c[2][4];
#pragma unroll
    for (int i = 0; i < 2; ++i)
#pragma unroll
        for (int j = 0; j < 4; ++j) wmma::fill_fragment(c[i][j], 0.f);

#pragma unroll
    for (int kk = 0; kk < 8; ++kk) {
        int k = kk * 16;
        wmma::fragment<wmma::matrix_a, 16, 16, 16, __half, wmma::row_major> a[2];
        wmma::fragment<wmma::matrix_b, 16, 16, 16, __half, wmma::col_major> b[4];
        wmma::load_matrix_sync(a[0], &xs[(wr +  0) * XS_LD + k], XS_LD);
        wmma::load_matrix_sync(a[1], &xs[(wr + 16) * XS_LD + k], XS_LD);
#pragma unroll
        for (int j = 0; j < 4; ++j)
            wmma::load_matrix_sync(b[j], &ws[(wc + j * 16) * XS_LD + k], XS_LD);
#pragma unroll
        for (int i = 0; i < 2; ++i)
#pragma unroll
            for (int j = 0; j < 4; ++j)
                wmma::mma_sync(c[i][j], a[i], b[j], c[i][j]);
    }
    __syncthreads();   // done reading xs/ws; reuse smem as csm

#pragma unroll
    for (int i = 0; i < 2; ++i)
#pragma unroll
        for (int j = 0; j < 4; ++j)
            wmma::store_matrix_sync(&csm[(wr + i * 16) * CS_LD + wc + j * 16],
                                    c[i][j], CS_LD, wmma::mem_row_major);
    __syncthreads();

    float4 alv = ((const float4*)al)[lane];   // [H,D] flat: cols lane*4..+3
    float4 arv = ((const float4*)ar)[lane];
    const int head = lane >> 3;

    for (int r = w; r < 128; r += 8) {
        int gn = n0 + r;
        float4 hv = *(float4*)&csm[r * CS_LD + lane * 4];

        if (gn < n_nodes) {
            g_h2[(size_t)gn * 64 + lane * 2]     = __floats2half2_rn(hv.x, hv.y);
            g_h2[(size_t)gn * 64 + lane * 2 + 1] = __floats2half2_rn(hv.z, hv.w);
        }

        float sl = hv.x * alv.x + hv.y * alv.y + hv.z * alv.z + hv.w * alv.w;
        float sr = hv.x * arv.x + hv.y * arv.y + hv.z * arv.z + hv.w * arv.w;
#pragma unroll
        for (int off = 1; off <= 4; off <<= 1) {
            sl += __shfl_xor_sync(0xffffffffu, sl, off);
            sr += __shfl_xor_sync(0xffffffffu, sr, off);
        }
        if ((lane & 7) == 0 && gn < n_nodes) {
            g_sl[(size_t)gn * NHEAD + head] = sl;
            g_sr[(size_t)gn * NHEAD + head] = sr;
        }
    }
}

// ---------------- K6: warp-per-node aggregation (ldcg h, MLP x8) ---------
__device__ __forceinline__ float lrelu_exp(float a)
{
    float t = (a > 0.f) ? a : 0.2f * a;
    return __expf(t);
}

__global__ __launch_bounds__(256)
void aggregate_kernel(float* __restrict__ out, int n_nodes, int n_edges)
{
    int warp = (blockIdx.x * blockDim.x + threadIdx.x) >> 5;
    int lane = threadIdx.x & 31;
    if (warp >= n_nodes) return;

    int beg = g_rowptr[warp];
    int end = g_rowptr[warp + 1];
    beg = min(max(beg, 0), n_edges);
    end = min(max(end, beg), n_edges);
    int head = lane >> 3;

    float srh = g_sr[(size_t)warp * NHEAD + head];

    const uint2* __restrict__ h4 = (const uint2*)g_h2;   // 4 halfs per lane
    const int*   __restrict__ csr = g_csr_src;

    float4 acc = make_float4(0.f, 0.f, 0.f, 0.f);
    float den = 0.f;

    int j = beg;
    for (; j + 7 < end; j += 8) {
        int   sx[8];
        float wx[8];
        uint2 ux[8];
#pragma unroll
        for (int q = 0; q < 8; ++q) sx[q] = csr[j + q];
#pragma unroll
        for (int q = 0; q < 8; ++q) wx[q] = g_sl[(size_t)sx[q] * NHEAD + head];
#pragma unroll
        for (int q = 0; q < 8; ++q) ux[q] = __ldcg(&h4[(size_t)sx[q] * 32 + lane]);
#pragma unroll
        for (int q = 0; q < 8; ++q) {
            float ee = lrelu_exp(wx[q] + srh);
            float2 a = __half22float2(*(__half2*)&ux[q].x);
            float2 b = __half22float2(*(__half2*)&ux[q].y);
            acc.x += a.x * ee; acc.y += a.y * ee;
            acc.z += b.x * ee; acc.w += b.y * ee;
            den += ee;
        }
    }
    for (; j < end; ++j) {
        int s = csr[j];
        float ee = lrelu_exp(g_sl[(size_t)s * NHEAD + head] + srh);
        uint2 u = __ldcg(&h4[(size_t)s * 32 + lane]);
        float2 a = __half22float2(*(__half2*)&u.x);
        float2 b = __half22float2(*(__half2*)&u.y);
        acc.x += a.x * ee; acc.y += a.y * ee;
        acc.z += b.x * ee; acc.w += b.y * ee;
        den += ee;
    }

    float inv = 1.f / (den + 1e-8f);
    float4 o = make_float4(acc.x * inv, acc.y * inv, acc.z * inv, acc.w * inv);
    *(float4*)&out[(size_t)warp * OUTF + lane * 4] = o;
}

// ---------------- launch ---------------------------------------------------
extern "C" void kernel_launch(void* const* d_in, const int* in_sizes, int n_in,
                              void* d_out, int out_size)
{
    const float* x   = (const float*)d_in[0];
    const int*   ei  = (const int*)d_in[1];     // int32 OR int64 (detected)
    const float* W   = (const float*)d_in[2];
    const float* al  = (const float*)d_in[3];
    const float* ar  = (const float*)d_in[4];
    float* out = (float*)d_out;

    int n_nodes = in_sizes[0] / INF_DIM;
    int n_edges = in_sizes[1] / 2;
    if (n_nodes > MAXN) n_nodes = MAXN;
    if (n_edges > MAXE) n_edges = MAXE;

    // one-time host resources (created on the uncaptured correctness call)
    static bool init = false;
    static cudaStream_t s2;
    static cudaEvent_t ev_fork, ev_join;
    if (!init) {
        cudaFuncSetAttribute(gemm_kernel,
                             cudaFuncAttributeMaxDynamicSharedMemorySize,
                             SMEM_GEMM);
        cudaStreamCreateWithFlags(&s2, cudaStreamNonBlocking);
        cudaEventCreateWithFlags(&ev_fork, cudaEventDisableTiming);
        cudaEventCreateWithFlags(&ev_join, cudaEventDisableTiming);
        init = true;
    }

    // fork: GEMM(+scalars) on side stream, edge chain on main stream
    cudaEventRecord(ev_fork, 0);
    cudaStreamWaitEvent(s2, ev_fork, 0);

    int gemm_blocks = (n_nodes + 127) / 128;
    gemm_kernel<<<gemm_blocks, 256, SMEM_GEMM, s2>>>(x, W, al, ar, n_nodes);
    cudaEventRecord(ev_join, s2);

    // edge chain (main stream): normalize -> scan -> scatter
    normalize_kernel<<<(n_edges + 255) / 256, 256>>>(ei, n_edges, n_nodes);
    int scan_blocks = (n_nodes + 1023) / 1024;
    scan1_kernel<<<scan_blocks, 1024>>>(n_nodes);
    scan3_kernel<<<(n_nodes + 255) / 256, 256>>>(n_nodes, n_edges, scan_blocks);
    scatter_kernel<<<(n_edges + 255) / 256, 256>>>(n_edges);

    // join: aggregate needs both CSR (main) and h/sl/sr (side)
    cudaStreamWaitEvent(0, ev_join, 0);
    int warps_blocks = (n_nodes * 32 + 255) / 256;
    aggregate_kernel<<<warps_blocks, 256>>>(out, n_nodes, n_edges);
}